// round 9
// baseline (speedup 1.0000x reference)
#include <cuda_runtime.h>
#include <cuda_fp16.h>
#include <stdint.h>
#include <math.h>

// Problem-fixed shapes
#define NNODES 100000
#define NEDGES 1600000
#define NGRAPH 512

// ---------------- scratch (device globals; no allocation) ----------------
__device__ int    d_deg[NNODES];
__device__ int    d_rowptr[NNODES + 1];
__device__ int    d_cursor[NNODES];
__device__ int    d_col[NEDGES];
__device__ float  d_dinv[NNODES];
__device__ __half d_hA[(size_t)NNODES * 64];
__device__ __half d_hB[(size_t)NNODES * 64];
__device__ float  d_g64[NGRAPH * 64];
__device__ int    d_bsum[256];

// ---------------- mma helpers ----------------
__device__ __forceinline__ uint32_t smem_u32(const void* p) {
    return (uint32_t)__cvta_generic_to_shared(p);
}
__device__ __forceinline__ void ldm_x4(uint32_t& r0, uint32_t& r1,
                                       uint32_t& r2, uint32_t& r3, uint32_t a) {
    asm volatile("ldmatrix.sync.aligned.m8n8.x4.shared.b16 {%0,%1,%2,%3}, [%4];"
                 : "=r"(r0), "=r"(r1), "=r"(r2), "=r"(r3) : "r"(a));
}
__device__ __forceinline__ void ldm_x4t(uint32_t& r0, uint32_t& r1,
                                        uint32_t& r2, uint32_t& r3, uint32_t a) {
    asm volatile("ldmatrix.sync.aligned.m8n8.x4.trans.shared.b16 {%0,%1,%2,%3}, [%4];"
                 : "=r"(r0), "=r"(r1), "=r"(r2), "=r"(r3) : "r"(a));
}
__device__ __forceinline__ void mma16816(float* c, const uint32_t* a,
                                         uint32_t b0, uint32_t b1) {
    asm volatile(
        "mma.sync.aligned.m16n8k16.row.col.f32.f16.f16.f32 "
        "{%0,%1,%2,%3}, {%4,%5,%6,%7}, {%8,%9}, {%0,%1,%2,%3};"
        : "+f"(c[0]), "+f"(c[1]), "+f"(c[2]), "+f"(c[3])
        : "r"(a[0]), "r"(a[1]), "r"(a[2]), "r"(a[3]), "r"(b0), "r"(b1));
}

// ---------------- zero + CSR build ----------------
__global__ void k_zero() {
    int i = blockIdx.x * blockDim.x + threadIdx.x;
    if (i < NNODES) d_deg[i] = 0;
    if (i < NGRAPH * 64) d_g64[i] = 0.f;
}

__global__ void k_deg(const int4* __restrict__ dst4) {
    int e = blockIdx.x * blockDim.x + threadIdx.x;
    if (e < NEDGES / 4) {
        int4 d = dst4[e];
        atomicAdd(&d_deg[d.x], 1);
        atomicAdd(&d_deg[d.y], 1);
        atomicAdd(&d_deg[d.z], 1);
        atomicAdd(&d_deg[d.w], 1);
    }
}

// block-local exclusive scan (512 elems per block)
__global__ void k_scan1() {
    __shared__ int s[512];
    int i = blockIdx.x * 512 + threadIdx.x;
    int v = (i < NNODES) ? d_deg[i] : 0;
    s[threadIdx.x] = v;
    __syncthreads();
    for (int off = 1; off < 512; off <<= 1) {
        int t = (threadIdx.x >= off) ? s[threadIdx.x - off] : 0;
        __syncthreads();
        s[threadIdx.x] += t;
        __syncthreads();
    }
    if (i < NNODES) d_rowptr[i] = s[threadIdx.x] - v;
    if (threadIdx.x == 511) d_bsum[blockIdx.x] = s[511];
}

// apply block offsets (each block re-sums partials; no separate scan2)
__global__ void k_scan3(int nblk) {
    __shared__ int soff;
    if (threadIdx.x == 0) {
        int a = 0;
        for (int b = 0; b < blockIdx.x; b++) a += d_bsum[b];
        soff = a;
        if (blockIdx.x == (int)gridDim.x - 1) {
            int tot = a;
            for (int b = blockIdx.x; b < nblk; b++) tot += d_bsum[b];
            d_rowptr[NNODES] = tot;
        }
    }
    __syncthreads();
    int i = blockIdx.x * 512 + threadIdx.x;
    if (i < NNODES) {
        int r = d_rowptr[i] + soff;
        d_rowptr[i] = r;
        d_cursor[i] = r;
        d_dinv[i] = rsqrtf((float)(d_deg[i] + 1));
    }
}

__global__ void k_scatter(const int4* __restrict__ src4,
                          const int4* __restrict__ dst4) {
    int e = blockIdx.x * blockDim.x + threadIdx.x;
    if (e < NEDGES / 4) {
        int4 s = src4[e];
        int4 d = dst4[e];
        d_col[atomicAdd(&d_cursor[d.x], 1)] = s.x;
        d_col[atomicAdd(&d_cursor[d.y], 1)] = s.y;
        d_col[atomicAdd(&d_cursor[d.z], 1)] = s.z;
        d_col[atomicAdd(&d_cursor[d.w], 1)] = s.w;
    }
}

// ---------------- GEMM1: Y1 = dinv * (x @ W1), tensor cores ----------------
// x fp32 [N,128] -> hA fp16 [N,32].  Block 256 thr / 8 warps, tile 128 rows.
__global__ __launch_bounds__(256) void k_mma1(const float* __restrict__ x,
                                              const float* __restrict__ W) {
    __shared__ __half Asm[128][136];  // 128x128 tile, k-contig, +8 pad
    __shared__ __half Wsm[128][40];   // 128x32 weights, +8 pad
    int tid = threadIdx.x;

    for (int i = tid; i < 128 * 32; i += 256)
        Wsm[i >> 5][i & 31] = __float2half(W[i]);

    int row0 = blockIdx.x * 128;
    for (int i = tid; i < 128 * 32; i += 256) {
        int r = i >> 5, c4 = i & 31;
        int gr = row0 + r;
        float4 v = (gr < NNODES)
            ? *reinterpret_cast<const float4*>(&x[(size_t)gr * 128 + c4 * 4])
            : make_float4(0.f, 0.f, 0.f, 0.f);
        __half2 h0 = __floats2half2_rn(v.x, v.y);
        __half2 h1 = __floats2half2_rn(v.z, v.w);
        uint2 pk;
        pk.x = *reinterpret_cast<uint32_t*>(&h0);
        pk.y = *reinterpret_cast<uint32_t*>(&h1);
        *reinterpret_cast<uint2*>(&Asm[r][c4 * 4]) = pk;
    }
    __syncthreads();

    int warp = tid >> 5, lane = tid & 31;
    float acc[4][4];
#pragma unroll
    for (int i = 0; i < 4; i++)
#pragma unroll
        for (int j = 0; j < 4; j++) acc[i][j] = 0.f;

    uint32_t aBase = smem_u32(&Asm[warp * 16 + (lane & 15)][(lane >> 4) * 8]);
#pragma unroll
    for (int ks = 0; ks < 8; ks++) {
        uint32_t a[4];
        ldm_x4(a[0], a[1], a[2], a[3], aBase + ks * 32);
#pragma unroll
        for (int nb = 0; nb < 2; nb++) {
            uint32_t b[4];
            uint32_t bAddr = smem_u32(&Wsm[ks * 16 + (lane & 15)][nb * 16 + (lane >> 4) * 8]);
            ldm_x4t(b[0], b[1], b[2], b[3], bAddr);
            mma16816(acc[nb * 2 + 0], a, b[0], b[1]);
            mma16816(acc[nb * 2 + 1], a, b[2], b[3]);
        }
    }

    int g = lane >> 2, t = lane & 3;
    int n0 = row0 + warp * 16 + g;
    int n1 = n0 + 8;
    float dv0 = (n0 < NNODES) ? d_dinv[n0] : 0.f;
    float dv1 = (n1 < NNODES) ? d_dinv[n1] : 0.f;
#pragma unroll
    for (int nt = 0; nt < 4; nt++) {
        int col = nt * 8 + t * 2;
        if (n0 < NNODES)
            *reinterpret_cast<__half2*>(&d_hA[(size_t)n0 * 32 + col]) =
                __floats2half2_rn(acc[nt][0] * dv0, acc[nt][1] * dv0);
        if (n1 < NNODES)
            *reinterpret_cast<__half2*>(&d_hA[(size_t)n1 * 32 + col]) =
                __floats2half2_rn(acc[nt][2] * dv1, acc[nt][3] * dv1);
    }
}

// ---------------- GEMM2: P2 = dinv * relu(Q2 @ W2 + b2), tensor cores ----
// hA fp16 [N,32] -> hB fp16 [N,64].
__global__ __launch_bounds__(256) void k_mma2(const float* __restrict__ W,
                                              const float* __restrict__ bias) {
    __shared__ __half Asm[128][40];
    __shared__ __half Wsm[32][72];
    __shared__ float bsm[64];
    int tid = threadIdx.x;

    for (int i = tid; i < 32 * 64; i += 256)
        Wsm[i >> 6][i & 63] = __float2half(W[i]);
    if (tid < 64) bsm[tid] = bias[tid];

    int row0 = blockIdx.x * 128;
    for (int i = tid; i < 512; i += 256) {
        int r = i >> 2, c8 = i & 3;
        int gr = row0 + r;
        uint4 v = (gr < NNODES)
            ? *reinterpret_cast<const uint4*>(&d_hA[(size_t)gr * 32 + c8 * 8])
            : make_uint4(0u, 0u, 0u, 0u);
        *reinterpret_cast<uint4*>(&Asm[r][c8 * 8]) = v;
    }
    __syncthreads();

    int warp = tid >> 5, lane = tid & 31;
    float acc[8][4];
#pragma unroll
    for (int i = 0; i < 8; i++)
#pragma unroll
        for (int j = 0; j < 4; j++) acc[i][j] = 0.f;

    uint32_t aBase = smem_u32(&Asm[warp * 16 + (lane & 15)][(lane >> 4) * 8]);
#pragma unroll
    for (int ks = 0; ks < 2; ks++) {
        uint32_t a[4];
        ldm_x4(a[0], a[1], a[2], a[3], aBase + ks * 32);
#pragma unroll
        for (int nb = 0; nb < 4; nb++) {
            uint32_t b[4];
            uint32_t bAddr = smem_u32(&Wsm[ks * 16 + (lane & 15)][nb * 16 + (lane >> 4) * 8]);
            ldm_x4t(b[0], b[1], b[2], b[3], bAddr);
            mma16816(acc[nb * 2 + 0], a, b[0], b[1]);
            mma16816(acc[nb * 2 + 1], a, b[2], b[3]);
        }
    }

    int g = lane >> 2, t = lane & 3;
    int n0 = row0 + warp * 16 + g;
    int n1 = n0 + 8;
    float dv0 = (n0 < NNODES) ? d_dinv[n0] : 0.f;
    float dv1 = (n1 < NNODES) ? d_dinv[n1] : 0.f;
#pragma unroll
    for (int nt = 0; nt < 8; nt++) {
        int col = nt * 8 + t * 2;
        float b0 = bsm[col], b1 = bsm[col + 1];
        if (n0 < NNODES) {
            float t0 = fmaxf(acc[nt][0] + b0, 0.f) * dv0;
            float t1 = fmaxf(acc[nt][1] + b1, 0.f) * dv0;
            *reinterpret_cast<__half2*>(&d_hB[(size_t)n0 * 64 + col]) = __floats2half2_rn(t0, t1);
        }
        if (n1 < NNODES) {
            float t0 = fmaxf(acc[nt][2] + b0, 0.f) * dv1;
            float t1 = fmaxf(acc[nt][3] + b1, 0.f) * dv1;
            *reinterpret_cast<__half2*>(&d_hB[(size_t)n1 * 64 + col]) = __floats2half2_rn(t0, t1);
        }
    }
}

// ---------------- sparse aggregation: fp16 gather, fp32 accum ----------
// L = F/8 lanes per node (16B = 8 halves per lane), G = 32/L nodes per warp.
template <int F, bool A_SRC, bool BIAS, bool RELU, bool POSTD>
__launch_bounds__(256)
__global__ void k_agg(const float* __restrict__ bias) {
    const uint4* __restrict__ Y = A_SRC ? (const uint4*)d_hA : (const uint4*)d_hB;
    uint4* __restrict__ O = A_SRC ? (uint4*)d_hB : (uint4*)d_hA;

    constexpr int L = F / 8;
    constexpr int G = 32 / L;
    constexpr int FV = F / 8;

    int warp = (blockIdx.x * 256 + threadIdx.x) >> 5;
    int lane = threadIdx.x & 31;
    int g = lane / L;
    int fl = lane % L;
    int node = warp * G + g;
    if (node >= NNODES) return;

    float acc[8];
    {
        uint4 v = __ldg(&Y[(size_t)node * FV + fl]);
        const __half2* h = reinterpret_cast<const __half2*>(&v);
#pragma unroll
        for (int q = 0; q < 4; q++) {
            float2 f = __half22float2(h[q]);
            acc[q * 2 + 0] = f.x;
            acc[q * 2 + 1] = f.y;
        }
    }

    int s = __ldg(&d_rowptr[node]);
    int e = __ldg(&d_rowptr[node + 1]);
#pragma unroll 2
    for (int j = s; j < e; j++) {
        int c = __ldg(&d_col[j]);
        uint4 v = __ldg(&Y[(size_t)c * FV + fl]);
        const __half2* h = reinterpret_cast<const __half2*>(&v);
#pragma unroll
        for (int q = 0; q < 4; q++) {
            float2 f = __half22float2(h[q]);
            acc[q * 2 + 0] += f.x;
            acc[q * 2 + 1] += f.y;
        }
    }

    float d = d_dinv[node];
    __half2 hv[4];
#pragma unroll
    for (int q = 0; q < 4; q++) {
        float t0 = acc[q * 2 + 0] * d;
        float t1 = acc[q * 2 + 1] * d;
        if (BIAS) { t0 += bias[fl * 8 + q * 2]; t1 += bias[fl * 8 + q * 2 + 1]; }
        if (RELU) { t0 = fmaxf(t0, 0.f); t1 = fmaxf(t1, 0.f); }
        if (POSTD) { t0 *= d; t1 *= d; }
        hv[q] = __floats2half2_rn(t0, t1);
    }
    O[(size_t)node * FV + fl] = *reinterpret_cast<uint4*>(hv);
}

// ---------------- agg3 fused with global_add_pool ----------------
// Q3[node] = dinv * sum(P2 over nbrs+self); atomically accumulate into g64[batch].
__launch_bounds__(256)
__global__ void k_agg64pool(const int* __restrict__ batch) {
    const uint4* __restrict__ Y = (const uint4*)d_hB;  // P2, F=64 -> 8 uint4/row
    int warp = (blockIdx.x * 256 + threadIdx.x) >> 5;
    int lane = threadIdx.x & 31;
    int g = lane >> 3;   // 4 nodes per warp
    int fl = lane & 7;   // 8 lanes per node
    int node = warp * 4 + g;
    if (node >= NNODES) return;

    float acc[8];
    {
        uint4 v = __ldg(&Y[(size_t)node * 8 + fl]);
        const __half2* h = reinterpret_cast<const __half2*>(&v);
#pragma unroll
        for (int q = 0; q < 4; q++) {
            float2 f = __half22float2(h[q]);
            acc[q * 2 + 0] = f.x;
            acc[q * 2 + 1] = f.y;
        }
    }
    int s = __ldg(&d_rowptr[node]);
    int e = __ldg(&d_rowptr[node + 1]);
#pragma unroll 2
    for (int j = s; j < e; j++) {
        int c = __ldg(&d_col[j]);
        uint4 v = __ldg(&Y[(size_t)c * 8 + fl]);
        const __half2* h = reinterpret_cast<const __half2*>(&v);
#pragma unroll
        for (int q = 0; q < 4; q++) {
            float2 f = __half22float2(h[q]);
            acc[q * 2 + 0] += f.x;
            acc[q * 2 + 1] += f.y;
        }
    }
    float d = d_dinv[node];
    int b = __ldg(&batch[node]);
    float* gp = &d_g64[b * 64 + fl * 8];
#pragma unroll
    for (int q = 0; q < 8; q++) atomicAdd(&gp[q], acc[q] * d);
}

// ---------------- GEMM3 (folded) + MLP head + log_softmax ----------------
__global__ void k_mlp(const int* __restrict__ batch,
                      const float* __restrict__ W3, const float* __restrict__ b3,
                      const float* __restrict__ Wl1, const float* __restrict__ bl1,
                      const float* __restrict__ Wl2, const float* __restrict__ bl2,
                      float* __restrict__ out) {
    __shared__ float g[64];
    __shared__ float h3[128];
    __shared__ float hid[64];
    __shared__ float o[10];
    __shared__ int cnt_s;
    int b = blockIdx.x, t = threadIdx.x;
    if (t < 64) g[t] = d_g64[b * 64 + t];
    if (t == 0) {
        int lo = 0, hi = NNODES;
        while (lo < hi) { int m = (lo + hi) >> 1; if (batch[m] < b) lo = m + 1; else hi = m; }
        int lb = lo;
        hi = NNODES;
        while (lo < hi) { int m = (lo + hi) >> 1; if (batch[m] <= b) lo = m + 1; else hi = m; }
        cnt_s = lo - lb;
    }
    __syncthreads();
    float nb = (float)cnt_s;
    {
        float a = nb * b3[t];
        for (int k = 0; k < 64; k++) a += g[k] * W3[k * 128 + t];
        h3[t] = a;
    }
    __syncthreads();
    if (t < 64) {
        float a = bl1[t];
        for (int k = 0; k < 128; k++) a += h3[k] * Wl1[k * 64 + t];
        hid[t] = fmaxf(a, 0.f);
    }
    __syncthreads();
    if (t < 10) {
        float a = bl2[t];
        for (int k = 0; k < 64; k++) a += hid[k] * Wl2[k * 10 + t];
        o[t] = a;
    }
    __syncthreads();
    if (t == 0) {
        float m = -INFINITY;
        for (int i = 0; i < 10; i++) m = fmaxf(m, o[i]);
        float s = 0.f;
        for (int i = 0; i < 10; i++) s += expf(o[i] - m);
        float l = m + logf(s);
        for (int i = 0; i < 10; i++) out[b * 10 + i] = o[i] - l;
    }
}

// ---------------- launch ----------------
extern "C" void kernel_launch(void* const* d_in, const int* in_sizes, int n_in,
                              void* d_out, int out_size) {
    const float* x     = (const float*)d_in[0];
    const int*   ei    = (const int*)d_in[1];
    const int*   batch = (const int*)d_in[2];
    const float* W1  = (const float*)d_in[3];
    const float* b1  = (const float*)d_in[4];
    const float* W2  = (const float*)d_in[5];
    const float* b2  = (const float*)d_in[6];
    const float* W3  = (const float*)d_in[7];
    const float* b3  = (const float*)d_in[8];
    const float* Wl1 = (const float*)d_in[9];
    const float* bl1 = (const float*)d_in[10];
    const float* Wl2 = (const float*)d_in[11];
    const float* bl2 = (const float*)d_in[12];
    float* out = (float*)d_out;

    const int4* src4 = (const int4*)ei;
    const int4* dst4 = (const int4*)(ei + NEDGES);

    const int NBLK_SCAN = (NNODES + 511) / 512;  // 196
    const int E4BLK = (NEDGES / 4 + 255) / 256;  // 1563
    const int AGG32_BLK = ((NNODES + 7) / 8 * 32 + 255) / 256;   // 1563
    const int AGG64_BLK = ((NNODES + 3) / 4 * 32 + 255) / 256;   // 3125
    const int MMABLK = (NNODES + 127) / 128;                     // 782

    // zero + CSR build + dinv
    k_zero<<<(NNODES + 255) / 256, 256>>>();
    k_deg<<<E4BLK, 256>>>(dst4);
    k_scan1<<<NBLK_SCAN, 512>>>();
    k_scan3<<<NBLK_SCAN, 512>>>(NBLK_SCAN);
    k_scatter<<<E4BLK, 256>>>(src4, dst4);

    // L1: Y1 = d*(x@W1)                  x -> hA     (tensor cores)
    k_mma1<<<MMABLK, 256>>>(x, W1);
    // agg1: P1 = d*relu(d*sum + b1)      hA -> hB    (F=32)
    k_agg<32, true, true, true, true><<<AGG32_BLK, 256>>>(b1);
    // agg2: Q2 = d*sum(P1)               hB -> hA    (F=32)
    k_agg<32, false, false, false, false><<<AGG32_BLK, 256>>>(nullptr);
    // L2: P2 = d*relu(Q2@W2 + b2)        hA -> hB    (tensor cores)
    k_mma2<<<MMABLK, 256>>>(W2, b2);
    // agg3 + pool: g64 += d*sum(P2)      hB -> d_g64
    k_agg64pool<<<AGG64_BLK, 256>>>(batch);

    // folded GEMM3 + MLP head (+ per-graph counts via binary search)
    k_mlp<<<NGRAPH, 128>>>(batch, W3, b3, Wl1, bl1, Wl2, bl2, out);
}

// round 11
// speedup vs baseline: 1.3696x; 1.3696x over previous
#include <cuda_runtime.h>
#include <cuda_fp16.h>
#include <stdint.h>
#include <math.h>

// Problem-fixed shapes
#define NNODES 100000
#define NEDGES 1600000
#define NGRAPH 512

// ---------------- scratch (device globals; no allocation) ----------------
__device__ int    d_deg[NNODES];
__device__ int    d_rowptr[NNODES + 1];
__device__ int    d_cursor[NNODES];
__device__ int    d_col[NEDGES];
__device__ float  d_dinv[NNODES];
__device__ __half d_hA[(size_t)NNODES * 64];
__device__ __half d_hB[(size_t)NNODES * 64];
__device__ float  d_g64[NGRAPH * 64];
__device__ int    d_bsum[256];

// ---------------- mma helpers ----------------
__device__ __forceinline__ uint32_t smem_u32(const void* p) {
    return (uint32_t)__cvta_generic_to_shared(p);
}
__device__ __forceinline__ void ldm_x4(uint32_t& r0, uint32_t& r1,
                                       uint32_t& r2, uint32_t& r3, uint32_t a) {
    asm volatile("ldmatrix.sync.aligned.m8n8.x4.shared.b16 {%0,%1,%2,%3}, [%4];"
                 : "=r"(r0), "=r"(r1), "=r"(r2), "=r"(r3) : "r"(a));
}
__device__ __forceinline__ void ldm_x4t(uint32_t& r0, uint32_t& r1,
                                        uint32_t& r2, uint32_t& r3, uint32_t a) {
    asm volatile("ldmatrix.sync.aligned.m8n8.x4.trans.shared.b16 {%0,%1,%2,%3}, [%4];"
                 : "=r"(r0), "=r"(r1), "=r"(r2), "=r"(r3) : "r"(a));
}
__device__ __forceinline__ void mma16816(float* c, const uint32_t* a,
                                         uint32_t b0, uint32_t b1) {
    asm volatile(
        "mma.sync.aligned.m16n8k16.row.col.f32.f16.f16.f32 "
        "{%0,%1,%2,%3}, {%4,%5,%6,%7}, {%8,%9}, {%0,%1,%2,%3};"
        : "+f"(c[0]), "+f"(c[1]), "+f"(c[2]), "+f"(c[3])
        : "r"(a[0]), "r"(a[1]), "r"(a[2]), "r"(a[3]), "r"(b0), "r"(b1));
}

// ---------------- zero + CSR build ----------------
__global__ void k_zero() {
    int i = blockIdx.x * blockDim.x + threadIdx.x;
    if (i < NNODES) d_deg[i] = 0;
}

__global__ void k_deg(const int4* __restrict__ dst4) {
    int e = blockIdx.x * blockDim.x + threadIdx.x;
    if (e < NEDGES / 4) {
        int4 d = dst4[e];
        atomicAdd(&d_deg[d.x], 1);
        atomicAdd(&d_deg[d.y], 1);
        atomicAdd(&d_deg[d.z], 1);
        atomicAdd(&d_deg[d.w], 1);
    }
}

// block-local exclusive scan (512 elems per block)
__global__ void k_scan1() {
    __shared__ int s[512];
    int i = blockIdx.x * 512 + threadIdx.x;
    int v = (i < NNODES) ? d_deg[i] : 0;
    s[threadIdx.x] = v;
    __syncthreads();
    for (int off = 1; off < 512; off <<= 1) {
        int t = (threadIdx.x >= off) ? s[threadIdx.x - off] : 0;
        __syncthreads();
        s[threadIdx.x] += t;
        __syncthreads();
    }
    if (i < NNODES) d_rowptr[i] = s[threadIdx.x] - v;
    if (threadIdx.x == 511) d_bsum[blockIdx.x] = s[511];
}

// apply block offsets; offset computed via parallel tree reduction
__global__ void k_scan3(int nblk) {
    __shared__ int red[512];
    int t = threadIdx.x;
    red[t] = (t < blockIdx.x) ? d_bsum[t] : 0;
    __syncthreads();
#pragma unroll
    for (int off = 256; off > 0; off >>= 1) {
        if (t < off) red[t] += red[t + off];
        __syncthreads();
    }
    int soff = red[0];
    __syncthreads();
    if (blockIdx.x == (int)gridDim.x - 1) {
        red[t] = (t < nblk) ? d_bsum[t] : 0;
        __syncthreads();
#pragma unroll
        for (int off = 256; off > 0; off >>= 1) {
            if (t < off) red[t] += red[t + off];
            __syncthreads();
        }
        if (t == 0) d_rowptr[NNODES] = red[0];
    }
    int i = blockIdx.x * 512 + t;
    if (i < NNODES) {
        int r = d_rowptr[i] + soff;
        d_rowptr[i] = r;
        d_cursor[i] = r;
        d_dinv[i] = rsqrtf((float)(d_deg[i] + 1));
    }
}

__global__ void k_scatter(const int4* __restrict__ src4,
                          const int4* __restrict__ dst4) {
    int e = blockIdx.x * blockDim.x + threadIdx.x;
    if (e < NGRAPH * 64) d_g64[e] = 0.f;  // zero pooled accum (free ride)
    if (e < NEDGES / 4) {
        int4 s = src4[e];
        int4 d = dst4[e];
        d_col[atomicAdd(&d_cursor[d.x], 1)] = s.x;
        d_col[atomicAdd(&d_cursor[d.y], 1)] = s.y;
        d_col[atomicAdd(&d_cursor[d.z], 1)] = s.z;
        d_col[atomicAdd(&d_cursor[d.w], 1)] = s.w;
    }
}

// ---------------- GEMM1: Y1 = dinv * (x @ W1), tensor cores ----------------
// x fp32 [N,128] -> hA fp16 [N,32].  Block 256 thr / 8 warps, tile 128 rows.
__global__ __launch_bounds__(256) void k_mma1(const float* __restrict__ x,
                                              const float* __restrict__ W) {
    __shared__ __half Asm[128][136];
    __shared__ __half Wsm[128][40];
    int tid = threadIdx.x;

    for (int i = tid; i < 128 * 32; i += 256)
        Wsm[i >> 5][i & 31] = __float2half(W[i]);

    int row0 = blockIdx.x * 128;
    for (int i = tid; i < 128 * 32; i += 256) {
        int r = i >> 5, c4 = i & 31;
        int gr = row0 + r;
        float4 v = (gr < NNODES)
            ? *reinterpret_cast<const float4*>(&x[(size_t)gr * 128 + c4 * 4])
            : make_float4(0.f, 0.f, 0.f, 0.f);
        __half2 h0 = __floats2half2_rn(v.x, v.y);
        __half2 h1 = __floats2half2_rn(v.z, v.w);
        uint2 pk;
        pk.x = *reinterpret_cast<uint32_t*>(&h0);
        pk.y = *reinterpret_cast<uint32_t*>(&h1);
        *reinterpret_cast<uint2*>(&Asm[r][c4 * 4]) = pk;
    }
    __syncthreads();

    int warp = tid >> 5, lane = tid & 31;
    float acc[4][4];
#pragma unroll
    for (int i = 0; i < 4; i++)
#pragma unroll
        for (int j = 0; j < 4; j++) acc[i][j] = 0.f;

    uint32_t aBase = smem_u32(&Asm[warp * 16 + (lane & 15)][(lane >> 4) * 8]);
#pragma unroll
    for (int ks = 0; ks < 8; ks++) {
        uint32_t a[4];
        ldm_x4(a[0], a[1], a[2], a[3], aBase + ks * 32);
#pragma unroll
        for (int nb = 0; nb < 2; nb++) {
            uint32_t b[4];
            uint32_t bAddr = smem_u32(&Wsm[ks * 16 + (lane & 15)][nb * 16 + (lane >> 4) * 8]);
            ldm_x4t(b[0], b[1], b[2], b[3], bAddr);
            mma16816(acc[nb * 2 + 0], a, b[0], b[1]);
            mma16816(acc[nb * 2 + 1], a, b[2], b[3]);
        }
    }

    int g = lane >> 2, t = lane & 3;
    int n0 = row0 + warp * 16 + g;
    int n1 = n0 + 8;
    float dv0 = (n0 < NNODES) ? d_dinv[n0] : 0.f;
    float dv1 = (n1 < NNODES) ? d_dinv[n1] : 0.f;
#pragma unroll
    for (int nt = 0; nt < 4; nt++) {
        int col = nt * 8 + t * 2;
        if (n0 < NNODES)
            *reinterpret_cast<__half2*>(&d_hA[(size_t)n0 * 32 + col]) =
                __floats2half2_rn(acc[nt][0] * dv0, acc[nt][1] * dv0);
        if (n1 < NNODES)
            *reinterpret_cast<__half2*>(&d_hA[(size_t)n1 * 32 + col]) =
                __floats2half2_rn(acc[nt][2] * dv1, acc[nt][3] * dv1);
    }
}

// ---------------- agg1: P1 = d*relu(d*sum + b1), hA -> hB, F=32 -----------
__launch_bounds__(256)
__global__ void k_agg1(const float* __restrict__ bias) {
    const uint4* __restrict__ Y = (const uint4*)d_hA;
    uint4* __restrict__ O = (uint4*)d_hB;

    int warp = (blockIdx.x * 256 + threadIdx.x) >> 5;
    int lane = threadIdx.x & 31;
    int g = lane >> 2;   // 8 nodes per warp
    int fl = lane & 3;   // 4 lanes per node (16B each)
    int node = warp * 8 + g;
    if (node >= NNODES) return;

    float acc[8];
    {
        uint4 v = __ldg(&Y[(size_t)node * 4 + fl]);
        const __half2* h = reinterpret_cast<const __half2*>(&v);
#pragma unroll
        for (int q = 0; q < 4; q++) {
            float2 f = __half22float2(h[q]);
            acc[q * 2 + 0] = f.x;
            acc[q * 2 + 1] = f.y;
        }
    }
    int s = __ldg(&d_rowptr[node]);
    int e = __ldg(&d_rowptr[node + 1]);
#pragma unroll 2
    for (int j = s; j < e; j++) {
        int c = __ldg(&d_col[j]);
        uint4 v = __ldg(&Y[(size_t)c * 4 + fl]);
        const __half2* h = reinterpret_cast<const __half2*>(&v);
#pragma unroll
        for (int q = 0; q < 4; q++) {
            float2 f = __half22float2(h[q]);
            acc[q * 2 + 0] += f.x;
            acc[q * 2 + 1] += f.y;
        }
    }

    float d = d_dinv[node];
    __half2 hv[4];
#pragma unroll
    for (int q = 0; q < 4; q++) {
        float t0 = acc[q * 2 + 0] * d + bias[fl * 8 + q * 2];
        float t1 = acc[q * 2 + 1] * d + bias[fl * 8 + q * 2 + 1];
        t0 = fmaxf(t0, 0.f) * d;
        t1 = fmaxf(t1, 0.f) * d;
        hv[q] = __floats2half2_rn(t0, t1);
    }
    O[(size_t)node * 4 + fl] = *reinterpret_cast<uint4*>(hv);
}

// ---------------- fused agg2 + GEMM2 --------------------------------------
// Phase 1: Q2[r] = d*sum(P1 over nbrs+self) for this block's 128 rows,
//          written straight into the mma A-tile in smem.
// Phase 2: P2 = d*relu(Q2 @ W2 + b2) via tensor cores -> hA.
__global__ __launch_bounds__(256) void k_agg2mma2(const float* __restrict__ W,
                                                  const float* __restrict__ bias) {
    __shared__ __half Asm[128][40];
    __shared__ __half Wsm[32][72];
    __shared__ float bsm[64];
    int tid = threadIdx.x;

    for (int i = tid; i < 32 * 64; i += 256)
        Wsm[i >> 6][i & 63] = __float2half(W[i]);
    if (tid < 64) bsm[tid] = bias[tid];

    const uint4* __restrict__ Y = (const uint4*)d_hB;  // P1, 4 uint4/row
    int row0 = blockIdx.x * 128;
    int warp = tid >> 5, lane = tid & 31;

    // phase 1: gather (8 nodes/warp, 4 lanes/node)
    {
        int g = lane >> 2, fl = lane & 3;
#pragma unroll
        for (int pass = 0; pass < 2; pass++) {
            int r = pass * 64 + warp * 8 + g;
            int node = row0 + r;
            float acc[8];
#pragma unroll
            for (int q = 0; q < 8; q++) acc[q] = 0.f;
            if (node < NNODES) {
                uint4 v = __ldg(&Y[(size_t)node * 4 + fl]);
                const __half2* h = reinterpret_cast<const __half2*>(&v);
#pragma unroll
                for (int q = 0; q < 4; q++) {
                    float2 f = __half22float2(h[q]);
                    acc[q * 2 + 0] = f.x;
                    acc[q * 2 + 1] = f.y;
                }
                int s = __ldg(&d_rowptr[node]);
                int e = __ldg(&d_rowptr[node + 1]);
#pragma unroll 2
                for (int j = s; j < e; j++) {
                    int c = __ldg(&d_col[j]);
                    uint4 vv = __ldg(&Y[(size_t)c * 4 + fl]);
                    const __half2* hh = reinterpret_cast<const __half2*>(&vv);
#pragma unroll
                    for (int q = 0; q < 4; q++) {
                        float2 f = __half22float2(hh[q]);
                        acc[q * 2 + 0] += f.x;
                        acc[q * 2 + 1] += f.y;
                    }
                }
                float d = d_dinv[node];
#pragma unroll
                for (int q = 0; q < 8; q++) acc[q] *= d;
            }
            __half2 hv[4];
#pragma unroll
            for (int q = 0; q < 4; q++)
                hv[q] = __floats2half2_rn(acc[q * 2], acc[q * 2 + 1]);
            *reinterpret_cast<uint4*>(&Asm[r][fl * 8]) = *reinterpret_cast<uint4*>(hv);
        }
    }
    __syncthreads();

    // phase 2: tensor-core GEMM
    float accm[8][4];
#pragma unroll
    for (int i = 0; i < 8; i++)
#pragma unroll
        for (int j = 0; j < 4; j++) accm[i][j] = 0.f;

    uint32_t aBase = smem_u32(&Asm[warp * 16 + (lane & 15)][(lane >> 4) * 8]);
#pragma unroll
    for (int ks = 0; ks < 2; ks++) {
        uint32_t a[4];
        ldm_x4(a[0], a[1], a[2], a[3], aBase + ks * 32);
#pragma unroll
        for (int nb = 0; nb < 4; nb++) {
            uint32_t b[4];
            uint32_t bAddr = smem_u32(&Wsm[ks * 16 + (lane & 15)][nb * 16 + (lane >> 4) * 8]);
            ldm_x4t(b[0], b[1], b[2], b[3], bAddr);
            mma16816(accm[nb * 2 + 0], a, b[0], b[1]);
            mma16816(accm[nb * 2 + 1], a, b[2], b[3]);
        }
    }

    int g2 = lane >> 2, t2 = lane & 3;
    int n0 = row0 + warp * 16 + g2;
    int n1 = n0 + 8;
    float dv0 = (n0 < NNODES) ? d_dinv[n0] : 0.f;
    float dv1 = (n1 < NNODES) ? d_dinv[n1] : 0.f;
#pragma unroll
    for (int nt = 0; nt < 8; nt++) {
        int col = nt * 8 + t2 * 2;
        float b0 = bsm[col], b1 = bsm[col + 1];
        if (n0 < NNODES) {
            float t0 = fmaxf(accm[nt][0] + b0, 0.f) * dv0;
            float t1 = fmaxf(accm[nt][1] + b1, 0.f) * dv0;
            *reinterpret_cast<__half2*>(&d_hA[(size_t)n0 * 64 + col]) = __floats2half2_rn(t0, t1);
        }
        if (n1 < NNODES) {
            float t0 = fmaxf(accm[nt][2] + b0, 0.f) * dv1;
            float t1 = fmaxf(accm[nt][3] + b1, 0.f) * dv1;
            *reinterpret_cast<__half2*>(&d_hA[(size_t)n1 * 64 + col]) = __floats2half2_rn(t0, t1);
        }
    }
}

// ---------------- agg3 fused with global_add_pool (warp-reduced atomics) ---
// Exactly 25000 full warps (100000 % 4 == 0): no divergent exits.
__launch_bounds__(256)
__global__ void k_agg64pool(const int* __restrict__ batch) {
    const uint4* __restrict__ Y = (const uint4*)d_hA;  // P2, 8 uint4/row
    int warp = (blockIdx.x * 256 + threadIdx.x) >> 5;
    int lane = threadIdx.x & 31;
    int g = lane >> 3;   // 4 nodes per warp
    int fl = lane & 7;   // 8 lanes per node
    int node = warp * 4 + g;   // always < NNODES (exact tiling)

    float acc[8];
    {
        uint4 v = __ldg(&Y[(size_t)node * 8 + fl]);
        const __half2* h = reinterpret_cast<const __half2*>(&v);
#pragma unroll
        for (int q = 0; q < 4; q++) {
            float2 f = __half22float2(h[q]);
            acc[q * 2 + 0] = f.x;
            acc[q * 2 + 1] = f.y;
        }
    }
    int s = __ldg(&d_rowptr[node]);
    int e = __ldg(&d_rowptr[node + 1]);
#pragma unroll 2
    for (int j = s; j < e; j++) {
        int c = __ldg(&d_col[j]);
        uint4 v = __ldg(&Y[(size_t)c * 8 + fl]);
        const __half2* h = reinterpret_cast<const __half2*>(&v);
#pragma unroll
        for (int q = 0; q < 4; q++) {
            float2 f = __half22float2(h[q]);
            acc[q * 2 + 0] += f.x;
            acc[q * 2 + 1] += f.y;
        }
    }
    float d = d_dinv[node];
#pragma unroll
    for (int q = 0; q < 8; q++) acc[q] *= d;

    int b = __ldg(&batch[node]);
    unsigned m = 0xffffffffu;
    // NOTE: both shuffles executed unconditionally by ALL lanes (no &&
    // short-circuit) — divergent shfl_xor_sync with a full mask deadlocks.
    int b8  = __shfl_xor_sync(m, b, 8);
    int b16 = __shfl_xor_sync(m, b, 16);
    bool uni = (b == b8) & (b == b16);
    if (__all_sync(m, uni)) {
        // all 4 nodes in warp belong to the same graph: reduce, 1/4 the atomics
#pragma unroll
        for (int q = 0; q < 8; q++) {
            acc[q] += __shfl_xor_sync(m, acc[q], 8);
            acc[q] += __shfl_xor_sync(m, acc[q], 16);
        }
        if (lane < 8) {
            float* gp = &d_g64[b * 64 + fl * 8];
#pragma unroll
            for (int q = 0; q < 8; q++) atomicAdd(&gp[q], acc[q]);
        }
    } else {
        float* gp = &d_g64[b * 64 + fl * 8];
#pragma unroll
        for (int q = 0; q < 8; q++) atomicAdd(&gp[q], acc[q]);
    }
}

// ---------------- GEMM3 (folded) + MLP head + log_softmax ----------------
__global__ void k_mlp(const int* __restrict__ batch,
                      const float* __restrict__ W3, const float* __restrict__ b3,
                      const float* __restrict__ Wl1, const float* __restrict__ bl1,
                      const float* __restrict__ Wl2, const float* __restrict__ bl2,
                      float* __restrict__ out) {
    __shared__ float g[64];
    __shared__ float h3[128];
    __shared__ float hid[64];
    __shared__ float o[10];
    __shared__ int cnt_s;
    int b = blockIdx.x, t = threadIdx.x;
    if (t < 64) g[t] = d_g64[b * 64 + t];
    if (t == 0) {
        int lo = 0, hi = NNODES;
        while (lo < hi) { int m = (lo + hi) >> 1; if (batch[m] < b) lo = m + 1; else hi = m; }
        int lb = lo;
        hi = NNODES;
        while (lo < hi) { int m = (lo + hi) >> 1; if (batch[m] <= b) lo = m + 1; else hi = m; }
        cnt_s = lo - lb;
    }
    __syncthreads();
    float nb = (float)cnt_s;
    {
        float a = nb * b3[t];
        for (int k = 0; k < 64; k++) a += g[k] * W3[k * 128 + t];
        h3[t] = a;
    }
    __syncthreads();
    if (t < 64) {
        float a = bl1[t];
        for (int k = 0; k < 128; k++) a += h3[k] * Wl1[k * 64 + t];
        hid[t] = fmaxf(a, 0.f);
    }
    __syncthreads();
    if (t < 10) {
        float a = bl2[t];
        for (int k = 0; k < 64; k++) a += hid[k] * Wl2[k * 10 + t];
        o[t] = a;
    }
    __syncthreads();
    if (t == 0) {
        float m = -INFINITY;
        for (int i = 0; i < 10; i++) m = fmaxf(m, o[i]);
        float s = 0.f;
        for (int i = 0; i < 10; i++) s += expf(o[i] - m);
        float l = m + logf(s);
        for (int i = 0; i < 10; i++) out[b * 10 + i] = o[i] - l;
    }
}

// ---------------- launch ----------------
extern "C" void kernel_launch(void* const* d_in, const int* in_sizes, int n_in,
                              void* d_out, int out_size) {
    const float* x     = (const float*)d_in[0];
    const int*   ei    = (const int*)d_in[1];
    const int*   batch = (const int*)d_in[2];
    const float* W1  = (const float*)d_in[3];
    const float* b1  = (const float*)d_in[4];
    const float* W2  = (const float*)d_in[5];
    const float* b2  = (const float*)d_in[6];
    const float* W3  = (const float*)d_in[7];
    const float* b3  = (const float*)d_in[8];
    const float* Wl1 = (const float*)d_in[9];
    const float* bl1 = (const float*)d_in[10];
    const float* Wl2 = (const float*)d_in[11];
    const float* bl2 = (const float*)d_in[12];
    float* out = (float*)d_out;

    const int4* src4 = (const int4*)ei;
    const int4* dst4 = (const int4*)(ei + NEDGES);

    const int NBLK_SCAN = (NNODES + 511) / 512;                // 196
    const int E4BLK = (NEDGES / 4 + 255) / 256;                // 1563
    const int AGG32_BLK = ((NNODES + 7) / 8 * 32 + 255) / 256; // 1563
    const int AGG64_BLK = (NNODES / 4 * 32) / 256;             // 3125 (exact)
    const int MMABLK = (NNODES + 127) / 128;                   // 782

    // CSR build + dinv
    k_zero<<<(NNODES + 255) / 256, 256>>>();
    k_deg<<<E4BLK, 256>>>(dst4);
    k_scan1<<<NBLK_SCAN, 512>>>();
    k_scan3<<<NBLK_SCAN, 512>>>(NBLK_SCAN);
    k_scatter<<<E4BLK, 256>>>(src4, dst4);

    // L1: Y1 = d*(x@W1)                      x -> hA   (tensor cores)
    k_mma1<<<MMABLK, 256>>>(x, W1);
    // agg1: P1 = d*relu(d*sum + b1)          hA -> hB
    k_agg1<<<AGG32_BLK, 256>>>(b1);
    // fused agg2+L2: P2 = d*relu((d*sum)@W2+b2)  hB -> hA
    k_agg2mma2<<<MMABLK, 256>>>(W2, b2);
    // agg3 + pool: g64 += d*sum(P2)          hA -> d_g64
    k_agg64pool<<<AGG64_BLK, 256>>>(batch);

    // folded GEMM3 + MLP head
    k_mlp<<<NGRAPH, 128>>>(batch, W3, b3, Wl1, bl1, Wl2, bl2, out);
}

// round 12
// speedup vs baseline: 1.4684x; 1.0721x over previous
#include <cuda_runtime.h>
#include <cuda_fp16.h>
#include <stdint.h>
#include <math.h>

// Problem-fixed shapes
#define NNODES 100000
#define NEDGES 1600000
#define NGRAPH 512

// ---------------- scratch (device globals; no allocation) ----------------
__device__ int    d_deg[NNODES];          // zero-init at load; restored to 0 each call
__device__ int    d_rowptr[NNODES + 1];
__device__ int    d_posin[NEDGES];
__device__ int    d_col[NEDGES];
__device__ float  d_dinv[NNODES];
__device__ __half d_hA[(size_t)NNODES * 64];
__device__ __half d_hB[(size_t)NNODES * 64];
__device__ float  d_g64[NGRAPH * 64];
__device__ int    d_bsum[256];

// ---------------- mma helpers ----------------
__device__ __forceinline__ uint32_t smem_u32(const void* p) {
    return (uint32_t)__cvta_generic_to_shared(p);
}
__device__ __forceinline__ void ldm_x4(uint32_t& r0, uint32_t& r1,
                                       uint32_t& r2, uint32_t& r3, uint32_t a) {
    asm volatile("ldmatrix.sync.aligned.m8n8.x4.shared.b16 {%0,%1,%2,%3}, [%4];"
                 : "=r"(r0), "=r"(r1), "=r"(r2), "=r"(r3) : "r"(a));
}
__device__ __forceinline__ void ldm_x4t(uint32_t& r0, uint32_t& r1,
                                        uint32_t& r2, uint32_t& r3, uint32_t a) {
    asm volatile("ldmatrix.sync.aligned.m8n8.x4.trans.shared.b16 {%0,%1,%2,%3}, [%4];"
                 : "=r"(r0), "=r"(r1), "=r"(r2), "=r"(r3) : "r"(a));
}
__device__ __forceinline__ void mma16816(float* c, const uint32_t* a,
                                         uint32_t b0, uint32_t b1) {
    asm volatile(
        "mma.sync.aligned.m16n8k16.row.col.f32.f16.f16.f32 "
        "{%0,%1,%2,%3}, {%4,%5,%6,%7}, {%8,%9}, {%0,%1,%2,%3};"
        : "+f"(c[0]), "+f"(c[1]), "+f"(c[2]), "+f"(c[3])
        : "r"(a[0]), "r"(a[1]), "r"(a[2]), "r"(a[3]), "r"(b0), "r"(b1));
}

// ---------------- CSR build ----------------
// degree count + per-edge position within its dst's list (free from the atomic)
__global__ void k_degpos(const int4* __restrict__ dst4) {
    int e = blockIdx.x * blockDim.x + threadIdx.x;
    if (e < NEDGES / 4) {
        int4 d = dst4[e];
        int4 p;
        p.x = atomicAdd(&d_deg[d.x], 1);
        p.y = atomicAdd(&d_deg[d.y], 1);
        p.z = atomicAdd(&d_deg[d.z], 1);
        p.w = atomicAdd(&d_deg[d.w], 1);
        reinterpret_cast<int4*>(d_posin)[e] = p;
    }
}

// block-local exclusive scan (512 elems per block)
__global__ void k_scan1() {
    __shared__ int s[512];
    int i = blockIdx.x * 512 + threadIdx.x;
    int v = (i < NNODES) ? d_deg[i] : 0;
    s[threadIdx.x] = v;
    __syncthreads();
    for (int off = 1; off < 512; off <<= 1) {
        int t = (threadIdx.x >= off) ? s[threadIdx.x - off] : 0;
        __syncthreads();
        s[threadIdx.x] += t;
        __syncthreads();
    }
    if (i < NNODES) d_rowptr[i] = s[threadIdx.x] - v;
    if (threadIdx.x == 511) d_bsum[blockIdx.x] = s[511];
}

// apply block offsets (tree-reduced), compute dinv, reset deg to 0 for next call
__global__ void k_scan3(int nblk) {
    __shared__ int red[512];
    int t = threadIdx.x;
    red[t] = (t < blockIdx.x) ? d_bsum[t] : 0;
    __syncthreads();
#pragma unroll
    for (int off = 256; off > 0; off >>= 1) {
        if (t < off) red[t] += red[t + off];
        __syncthreads();
    }
    int soff = red[0];
    __syncthreads();
    if (blockIdx.x == (int)gridDim.x - 1) {
        red[t] = (t < nblk) ? d_bsum[t] : 0;
        __syncthreads();
#pragma unroll
        for (int off = 256; off > 0; off >>= 1) {
            if (t < off) red[t] += red[t + off];
            __syncthreads();
        }
        if (t == 0) d_rowptr[NNODES] = red[0];
    }
    int i = blockIdx.x * 512 + t;
    if (i < NNODES) {
        d_rowptr[i] += soff;
        d_dinv[i] = rsqrtf((float)(d_deg[i] + 1));
        d_deg[i] = 0;   // restore invariant (zero-init) for next call
    }
}

// atomic-free scatter: pos = rowptr[dst] + posin[e]
__global__ void k_scatter(const int4* __restrict__ src4,
                          const int4* __restrict__ dst4) {
    int e = blockIdx.x * blockDim.x + threadIdx.x;
    if (e < NGRAPH * 64) d_g64[e] = 0.f;  // zero pooled accum (free ride)
    if (e < NEDGES / 4) {
        int4 s = src4[e];
        int4 d = dst4[e];
        int4 p = reinterpret_cast<const int4*>(d_posin)[e];
        d_col[d_rowptr[d.x] + p.x] = s.x;
        d_col[d_rowptr[d.y] + p.y] = s.y;
        d_col[d_rowptr[d.z] + p.z] = s.z;
        d_col[d_rowptr[d.w] + p.w] = s.w;
    }
}

// ---------------- GEMM1: Y1 = dinv * (x @ W1), tensor cores ----------------
__global__ __launch_bounds__(256) void k_mma1(const float* __restrict__ x,
                                              const float* __restrict__ W) {
    __shared__ __half Asm[128][136];
    __shared__ __half Wsm[128][40];
    int tid = threadIdx.x;

    for (int i = tid; i < 128 * 32; i += 256)
        Wsm[i >> 5][i & 31] = __float2half(W[i]);

    int row0 = blockIdx.x * 128;
    for (int i = tid; i < 128 * 32; i += 256) {
        int r = i >> 5, c4 = i & 31;
        int gr = row0 + r;
        float4 v = (gr < NNODES)
            ? *reinterpret_cast<const float4*>(&x[(size_t)gr * 128 + c4 * 4])
            : make_float4(0.f, 0.f, 0.f, 0.f);
        __half2 h0 = __floats2half2_rn(v.x, v.y);
        __half2 h1 = __floats2half2_rn(v.z, v.w);
        uint2 pk;
        pk.x = *reinterpret_cast<uint32_t*>(&h0);
        pk.y = *reinterpret_cast<uint32_t*>(&h1);
        *reinterpret_cast<uint2*>(&Asm[r][c4 * 4]) = pk;
    }
    __syncthreads();

    int warp = tid >> 5, lane = tid & 31;
    float acc[4][4];
#pragma unroll
    for (int i = 0; i < 4; i++)
#pragma unroll
        for (int j = 0; j < 4; j++) acc[i][j] = 0.f;

    uint32_t aBase = smem_u32(&Asm[warp * 16 + (lane & 15)][(lane >> 4) * 8]);
#pragma unroll
    for (int ks = 0; ks < 8; ks++) {
        uint32_t a[4];
        ldm_x4(a[0], a[1], a[2], a[3], aBase + ks * 32);
#pragma unroll
        for (int nb = 0; nb < 2; nb++) {
            uint32_t b[4];
            uint32_t bAddr = smem_u32(&Wsm[ks * 16 + (lane & 15)][nb * 16 + (lane >> 4) * 8]);
            ldm_x4t(b[0], b[1], b[2], b[3], bAddr);
            mma16816(acc[nb * 2 + 0], a, b[0], b[1]);
            mma16816(acc[nb * 2 + 1], a, b[2], b[3]);
        }
    }

    int g = lane >> 2, t = lane & 3;
    int n0 = row0 + warp * 16 + g;
    int n1 = n0 + 8;
    float dv0 = (n0 < NNODES) ? d_dinv[n0] : 0.f;
    float dv1 = (n1 < NNODES) ? d_dinv[n1] : 0.f;
#pragma unroll
    for (int nt = 0; nt < 4; nt++) {
        int col = nt * 8 + t * 2;
        if (n0 < NNODES)
            *reinterpret_cast<__half2*>(&d_hA[(size_t)n0 * 32 + col]) =
                __floats2half2_rn(acc[nt][0] * dv0, acc[nt][1] * dv0);
        if (n1 < NNODES)
            *reinterpret_cast<__half2*>(&d_hA[(size_t)n1 * 32 + col]) =
                __floats2half2_rn(acc[nt][2] * dv1, acc[nt][3] * dv1);
    }
}

// ---------------- agg1: P1 = d*relu(d*sum + b1), hA -> hB, F=32 -----------
__launch_bounds__(256)
__global__ void k_agg1(const float* __restrict__ bias) {
    const uint4* __restrict__ Y = (const uint4*)d_hA;
    uint4* __restrict__ O = (uint4*)d_hB;

    int warp = (blockIdx.x * 256 + threadIdx.x) >> 5;
    int lane = threadIdx.x & 31;
    int g = lane >> 2;   // 8 nodes per warp
    int fl = lane & 3;   // 4 lanes per node (16B each)
    int node = warp * 8 + g;
    if (node >= NNODES) return;

    float acc[8];
    {
        uint4 v = __ldg(&Y[(size_t)node * 4 + fl]);
        const __half2* h = reinterpret_cast<const __half2*>(&v);
#pragma unroll
        for (int q = 0; q < 4; q++) {
            float2 f = __half22float2(h[q]);
            acc[q * 2 + 0] = f.x;
            acc[q * 2 + 1] = f.y;
        }
    }
    int s = __ldg(&d_rowptr[node]);
    int e = __ldg(&d_rowptr[node + 1]);
#pragma unroll 2
    for (int j = s; j < e; j++) {
        int c = __ldg(&d_col[j]);
        uint4 v = __ldg(&Y[(size_t)c * 4 + fl]);
        const __half2* h = reinterpret_cast<const __half2*>(&v);
#pragma unroll
        for (int q = 0; q < 4; q++) {
            float2 f = __half22float2(h[q]);
            acc[q * 2 + 0] += f.x;
            acc[q * 2 + 1] += f.y;
        }
    }

    float d = d_dinv[node];
    __half2 hv[4];
#pragma unroll
    for (int q = 0; q < 4; q++) {
        float t0 = acc[q * 2 + 0] * d + bias[fl * 8 + q * 2];
        float t1 = acc[q * 2 + 1] * d + bias[fl * 8 + q * 2 + 1];
        t0 = fmaxf(t0, 0.f) * d;
        t1 = fmaxf(t1, 0.f) * d;
        hv[q] = __floats2half2_rn(t0, t1);
    }
    O[(size_t)node * 4 + fl] = *reinterpret_cast<uint4*>(hv);
}

// ---------------- fused agg2 + GEMM2 --------------------------------------
__global__ __launch_bounds__(256) void k_agg2mma2(const float* __restrict__ W,
                                                  const float* __restrict__ bias) {
    __shared__ __half Asm[128][40];
    __shared__ __half Wsm[32][72];
    __shared__ float bsm[64];
    int tid = threadIdx.x;

    for (int i = tid; i < 32 * 64; i += 256)
        Wsm[i >> 6][i & 63] = __float2half(W[i]);
    if (tid < 64) bsm[tid] = bias[tid];

    const uint4* __restrict__ Y = (const uint4*)d_hB;  // P1, 4 uint4/row
    int row0 = blockIdx.x * 128;
    int warp = tid >> 5, lane = tid & 31;

    // phase 1: gather (8 nodes/warp, 4 lanes/node)
    {
        int g = lane >> 2, fl = lane & 3;
#pragma unroll
        for (int pass = 0; pass < 2; pass++) {
            int r = pass * 64 + warp * 8 + g;
            int node = row0 + r;
            float acc[8];
#pragma unroll
            for (int q = 0; q < 8; q++) acc[q] = 0.f;
            if (node < NNODES) {
                uint4 v = __ldg(&Y[(size_t)node * 4 + fl]);
                const __half2* h = reinterpret_cast<const __half2*>(&v);
#pragma unroll
                for (int q = 0; q < 4; q++) {
                    float2 f = __half22float2(h[q]);
                    acc[q * 2 + 0] = f.x;
                    acc[q * 2 + 1] = f.y;
                }
                int s = __ldg(&d_rowptr[node]);
                int e = __ldg(&d_rowptr[node + 1]);
#pragma unroll 2
                for (int j = s; j < e; j++) {
                    int c = __ldg(&d_col[j]);
                    uint4 vv = __ldg(&Y[(size_t)c * 4 + fl]);
                    const __half2* hh = reinterpret_cast<const __half2*>(&vv);
#pragma unroll
                    for (int q = 0; q < 4; q++) {
                        float2 f = __half22float2(hh[q]);
                        acc[q * 2 + 0] += f.x;
                        acc[q * 2 + 1] += f.y;
                    }
                }
                float d = d_dinv[node];
#pragma unroll
                for (int q = 0; q < 8; q++) acc[q] *= d;
            }
            __half2 hv[4];
#pragma unroll
            for (int q = 0; q < 4; q++)
                hv[q] = __floats2half2_rn(acc[q * 2], acc[q * 2 + 1]);
            *reinterpret_cast<uint4*>(&Asm[r][fl * 8]) = *reinterpret_cast<uint4*>(hv);
        }
    }
    __syncthreads();

    // phase 2: tensor-core GEMM
    float accm[8][4];
#pragma unroll
    for (int i = 0; i < 8; i++)
#pragma unroll
        for (int j = 0; j < 4; j++) accm[i][j] = 0.f;

    uint32_t aBase = smem_u32(&Asm[warp * 16 + (lane & 15)][(lane >> 4) * 8]);
#pragma unroll
    for (int ks = 0; ks < 2; ks++) {
        uint32_t a[4];
        ldm_x4(a[0], a[1], a[2], a[3], aBase + ks * 32);
#pragma unroll
        for (int nb = 0; nb < 4; nb++) {
            uint32_t b[4];
            uint32_t bAddr = smem_u32(&Wsm[ks * 16 + (lane & 15)][nb * 16 + (lane >> 4) * 8]);
            ldm_x4t(b[0], b[1], b[2], b[3], bAddr);
            mma16816(accm[nb * 2 + 0], a, b[0], b[1]);
            mma16816(accm[nb * 2 + 1], a, b[2], b[3]);
        }
    }

    int g2 = lane >> 2, t2 = lane & 3;
    int n0 = row0 + warp * 16 + g2;
    int n1 = n0 + 8;
    float dv0 = (n0 < NNODES) ? d_dinv[n0] : 0.f;
    float dv1 = (n1 < NNODES) ? d_dinv[n1] : 0.f;
#pragma unroll
    for (int nt = 0; nt < 8; nt++) {
        int col = nt * 8 + t2 * 2;
        float b0 = bsm[col], b1 = bsm[col + 1];
        if (n0 < NNODES) {
            float t0 = fmaxf(accm[nt][0] + b0, 0.f) * dv0;
            float t1 = fmaxf(accm[nt][1] + b1, 0.f) * dv0;
            *reinterpret_cast<__half2*>(&d_hA[(size_t)n0 * 64 + col]) = __floats2half2_rn(t0, t1);
        }
        if (n1 < NNODES) {
            float t0 = fmaxf(accm[nt][2] + b0, 0.f) * dv1;
            float t1 = fmaxf(accm[nt][3] + b1, 0.f) * dv1;
            *reinterpret_cast<__half2*>(&d_hA[(size_t)n1 * 64 + col]) = __floats2half2_rn(t0, t1);
        }
    }
}

// ---------------- agg3 fused with global_add_pool --------------------------
// warp-level + block-level reduction of atomics (batch sorted => mostly uniform).
// Exact tiling (100000 % 4 == 0): all 256 threads alive; __syncthreads safe.
__launch_bounds__(256)
__global__ void k_agg64pool(const int* __restrict__ batch) {
    const uint4* __restrict__ Y = (const uint4*)d_hA;  // P2, 8 uint4/row
    __shared__ float red[8][64];
    __shared__ int bsh[8];

    int tid = threadIdx.x;
    int warpid = tid >> 5;
    int warp = (blockIdx.x * 256 + tid) >> 5;
    int lane = tid & 31;
    int g = lane >> 3;   // 4 nodes per warp
    int fl = lane & 7;   // 8 lanes per node
    int node = warp * 4 + g;

    float acc[8];
    {
        uint4 v = __ldg(&Y[(size_t)node * 8 + fl]);
        const __half2* h = reinterpret_cast<const __half2*>(&v);
#pragma unroll
        for (int q = 0; q < 4; q++) {
            float2 f = __half22float2(h[q]);
            acc[q * 2 + 0] = f.x;
            acc[q * 2 + 1] = f.y;
        }
    }
    int s = __ldg(&d_rowptr[node]);
    int e = __ldg(&d_rowptr[node + 1]);
#pragma unroll 2
    for (int j = s; j < e; j++) {
        int c = __ldg(&d_col[j]);
        uint4 v = __ldg(&Y[(size_t)c * 8 + fl]);
        const __half2* h = reinterpret_cast<const __half2*>(&v);
#pragma unroll
        for (int q = 0; q < 4; q++) {
            float2 f = __half22float2(h[q]);
            acc[q * 2 + 0] += f.x;
            acc[q * 2 + 1] += f.y;
        }
    }
    float d = d_dinv[node];
#pragma unroll
    for (int q = 0; q < 8; q++) acc[q] *= d;

    int b = __ldg(&batch[node]);
    unsigned m = 0xffffffffu;
    // both shuffles unconditional (no && short-circuit -> no divergent-shfl hang)
    int b8  = __shfl_xor_sync(m, b, 8);
    int b16 = __shfl_xor_sync(m, b, 16);
    bool uni = (b == b8) & (b == b16);
    bool wuni = __all_sync(m, uni);

    if (lane == 0) bsh[warpid] = wuni ? b : -1;
    __syncthreads();
    int b0 = bsh[0];
    bool blockuni = (b0 >= 0);
#pragma unroll
    for (int w = 1; w < 8; w++) blockuni &= (bsh[w] == b0);

    if (blockuni) {
        // reduce 4 nodes within warp, stage 8 lanes x 8 floats into smem
#pragma unroll
        for (int q = 0; q < 8; q++) {
            acc[q] += __shfl_xor_sync(m, acc[q], 8);
            acc[q] += __shfl_xor_sync(m, acc[q], 16);
        }
        if (lane < 8) {
#pragma unroll
            for (int q = 0; q < 8; q++) red[warpid][lane * 8 + q] = acc[q];
        }
    }
    __syncthreads();
    if (blockuni) {
        // 64 atomics for the whole block (32 nodes)
        if (tid < 64) {
            float sum = 0.f;
#pragma unroll
            for (int w = 0; w < 8; w++) sum += red[w][tid];
            atomicAdd(&d_g64[b0 * 64 + tid], sum);
        }
    } else {
        if (wuni) {
#pragma unroll
            for (int q = 0; q < 8; q++) {
                acc[q] += __shfl_xor_sync(m, acc[q], 8);
                acc[q] += __shfl_xor_sync(m, acc[q], 16);
            }
            if (lane < 8) {
                float* gp = &d_g64[b * 64 + fl * 8];
#pragma unroll
                for (int q = 0; q < 8; q++) atomicAdd(&gp[q], acc[q]);
            }
        } else {
            float* gp = &d_g64[b * 64 + fl * 8];
#pragma unroll
            for (int q = 0; q < 8; q++) atomicAdd(&gp[q], acc[q]);
        }
    }
}

// ---------------- GEMM3 (folded) + MLP head + log_softmax ----------------
__global__ void k_mlp(const int* __restrict__ batch,
                      const float* __restrict__ W3, const float* __restrict__ b3,
                      const float* __restrict__ Wl1, const float* __restrict__ bl1,
                      const float* __restrict__ Wl2, const float* __restrict__ bl2,
                      float* __restrict__ out) {
    __shared__ float g[64];
    __shared__ float h3[128];
    __shared__ float hid[64];
    __shared__ float o[10];
    __shared__ int cnt_s;
    int b = blockIdx.x, t = threadIdx.x;
    if (t < 64) g[t] = d_g64[b * 64 + t];
    if (t == 0) {
        int lo = 0, hi = NNODES;
        while (lo < hi) { int m = (lo + hi) >> 1; if (batch[m] < b) lo = m + 1; else hi = m; }
        int lb = lo;
        hi = NNODES;
        while (lo < hi) { int m = (lo + hi) >> 1; if (batch[m] <= b) lo = m + 1; else hi = m; }
        cnt_s = lo - lb;
    }
    __syncthreads();
    float nb = (float)cnt_s;
    {
        float a = nb * b3[t];
        for (int k = 0; k < 64; k++) a += g[k] * W3[k * 128 + t];
        h3[t] = a;
    }
    __syncthreads();
    if (t < 64) {
        float a = bl1[t];
        for (int k = 0; k < 128; k++) a += h3[k] * Wl1[k * 64 + t];
        hid[t] = fmaxf(a, 0.f);
    }
    __syncthreads();
    if (t < 10) {
        float a = bl2[t];
        for (int k = 0; k < 64; k++) a += hid[k] * Wl2[k * 10 + t];
        o[t] = a;
    }
    __syncthreads();
    if (t == 0) {
        float m = -INFINITY;
        for (int i = 0; i < 10; i++) m = fmaxf(m, o[i]);
        float s = 0.f;
        for (int i = 0; i < 10; i++) s += expf(o[i] - m);
        float l = m + logf(s);
        for (int i = 0; i < 10; i++) out[b * 10 + i] = o[i] - l;
    }
}

// ---------------- launch ----------------
extern "C" void kernel_launch(void* const* d_in, const int* in_sizes, int n_in,
                              void* d_out, int out_size) {
    const float* x     = (const float*)d_in[0];
    const int*   ei    = (const int*)d_in[1];
    const int*   batch = (const int*)d_in[2];
    const float* W1  = (const float*)d_in[3];
    const float* b1  = (const float*)d_in[4];
    const float* W2  = (const float*)d_in[5];
    const float* b2  = (const float*)d_in[6];
    const float* W3  = (const float*)d_in[7];
    const float* b3  = (const float*)d_in[8];
    const float* Wl1 = (const float*)d_in[9];
    const float* bl1 = (const float*)d_in[10];
    const float* Wl2 = (const float*)d_in[11];
    const float* bl2 = (const float*)d_in[12];
    float* out = (float*)d_out;

    const int4* src4 = (const int4*)ei;
    const int4* dst4 = (const int4*)(ei + NEDGES);

    const int NBLK_SCAN = (NNODES + 511) / 512;                // 196
    const int E4BLK = (NEDGES / 4 + 255) / 256;                // 1563
    const int AGG32_BLK = ((NNODES + 7) / 8 * 32 + 255) / 256; // 1563
    const int AGG64_BLK = (NNODES / 4 * 32) / 256;             // 3125 (exact)
    const int MMABLK = (NNODES + 127) / 128;                   // 782

    // CSR build (deg zeroed by previous call's k_scan3 / module-load init)
    k_degpos<<<E4BLK, 256>>>(dst4);
    k_scan1<<<NBLK_SCAN, 512>>>();
    k_scan3<<<NBLK_SCAN, 512>>>(NBLK_SCAN);
    k_scatter<<<E4BLK, 256>>>(src4, dst4);

    // L1: Y1 = d*(x@W1)                      x -> hA   (tensor cores)
    k_mma1<<<MMABLK, 256>>>(x, W1);
    // agg1: P1 = d*relu(d*sum + b1)          hA -> hB
    k_agg1<<<AGG32_BLK, 256>>>(b1);
    // fused agg2+L2: P2 = d*relu((d*sum)@W2+b2)  hB -> hA
    k_agg2mma2<<<MMABLK, 256>>>(W2, b2);
    // agg3 + pool: g64 += d*sum(P2)          hA -> d_g64
    k_agg64pool<<<AGG64_BLK, 256>>>(batch);

    // folded GEMM3 + MLP head
    k_mlp<<<NGRAPH, 128>>>(batch, W3, b3, Wl1, bl1, Wl2, bl2, out);
}

// round 13
// speedup vs baseline: 1.4973x; 1.0197x over previous
#include <cuda_runtime.h>
#include <cuda_fp16.h>
#include <stdint.h>
#include <math.h>

// Problem-fixed shapes
#define NNODES 100000
#define NEDGES 1600000
#define NGRAPH 512

// ---------------- scratch (device globals; no allocation) ----------------
__device__ int    d_deg[NNODES];          // zero-init at load; restored to 0 each call
__device__ int    d_rowptr[NNODES + 1];
__device__ int    d_posin[NEDGES];
__device__ int    d_col[NEDGES];
__device__ float  d_dinv[NNODES];
__device__ __half d_hA[(size_t)NNODES * 64];
__device__ __half d_hB[(size_t)NNODES * 64];
__device__ float  d_g64[NGRAPH * 64];
__device__ int    d_bsum[256];

// ---------------- mma helpers ----------------
__device__ __forceinline__ uint32_t smem_u32(const void* p) {
    return (uint32_t)__cvta_generic_to_shared(p);
}
__device__ __forceinline__ void ldm_x4(uint32_t& r0, uint32_t& r1,
                                       uint32_t& r2, uint32_t& r3, uint32_t a) {
    asm volatile("ldmatrix.sync.aligned.m8n8.x4.shared.b16 {%0,%1,%2,%3}, [%4];"
                 : "=r"(r0), "=r"(r1), "=r"(r2), "=r"(r3) : "r"(a));
}
__device__ __forceinline__ void ldm_x4t(uint32_t& r0, uint32_t& r1,
                                        uint32_t& r2, uint32_t& r3, uint32_t a) {
    asm volatile("ldmatrix.sync.aligned.m8n8.x4.trans.shared.b16 {%0,%1,%2,%3}, [%4];"
                 : "=r"(r0), "=r"(r1), "=r"(r2), "=r"(r3) : "r"(a));
}
__device__ __forceinline__ void mma16816(float* c, const uint32_t* a,
                                         uint32_t b0, uint32_t b1) {
    asm volatile(
        "mma.sync.aligned.m16n8k16.row.col.f32.f16.f16.f32 "
        "{%0,%1,%2,%3}, {%4,%5,%6,%7}, {%8,%9}, {%0,%1,%2,%3};"
        : "+f"(c[0]), "+f"(c[1]), "+f"(c[2]), "+f"(c[3])
        : "r"(a[0]), "r"(a[1]), "r"(a[2]), "r"(a[3]), "r"(b0), "r"(b1));
}

// accumulate a uint4 of 8 halves into 8 fp32 accumulators
__device__ __forceinline__ void acc8(float* acc, uint4 v) {
    const __half2* h = reinterpret_cast<const __half2*>(&v);
#pragma unroll
    for (int q = 0; q < 4; q++) {
        float2 f = __half22float2(h[q]);
        acc[q * 2 + 0] += f.x;
        acc[q * 2 + 1] += f.y;
    }
}

// ---------------- CSR build ----------------
__global__ void k_degpos(const int4* __restrict__ dst4) {
    int e = blockIdx.x * blockDim.x + threadIdx.x;
    if (e < NEDGES / 4) {
        int4 d = dst4[e];
        int4 p;
        p.x = atomicAdd(&d_deg[d.x], 1);
        p.y = atomicAdd(&d_deg[d.y], 1);
        p.z = atomicAdd(&d_deg[d.z], 1);
        p.w = atomicAdd(&d_deg[d.w], 1);
        reinterpret_cast<int4*>(d_posin)[e] = p;
    }
}

__global__ void k_scan1() {
    __shared__ int s[512];
    int i = blockIdx.x * 512 + threadIdx.x;
    int v = (i < NNODES) ? d_deg[i] : 0;
    s[threadIdx.x] = v;
    __syncthreads();
    for (int off = 1; off < 512; off <<= 1) {
        int t = (threadIdx.x >= off) ? s[threadIdx.x - off] : 0;
        __syncthreads();
        s[threadIdx.x] += t;
        __syncthreads();
    }
    if (i < NNODES) d_rowptr[i] = s[threadIdx.x] - v;
    if (threadIdx.x == 511) d_bsum[blockIdx.x] = s[511];
}

__global__ void k_scan3(int nblk) {
    __shared__ int red[512];
    int t = threadIdx.x;
    red[t] = (t < blockIdx.x) ? d_bsum[t] : 0;
    __syncthreads();
#pragma unroll
    for (int off = 256; off > 0; off >>= 1) {
        if (t < off) red[t] += red[t + off];
        __syncthreads();
    }
    int soff = red[0];
    __syncthreads();
    if (blockIdx.x == (int)gridDim.x - 1) {
        red[t] = (t < nblk) ? d_bsum[t] : 0;
        __syncthreads();
#pragma unroll
        for (int off = 256; off > 0; off >>= 1) {
            if (t < off) red[t] += red[t + off];
            __syncthreads();
        }
        if (t == 0) d_rowptr[NNODES] = red[0];
    }
    int i = blockIdx.x * 512 + t;
    if (i < NNODES) {
        d_rowptr[i] += soff;
        d_dinv[i] = rsqrtf((float)(d_deg[i] + 1));
        d_deg[i] = 0;   // restore invariant for next call
    }
}

__global__ void k_scatter(const int4* __restrict__ src4,
                          const int4* __restrict__ dst4) {
    int e = blockIdx.x * blockDim.x + threadIdx.x;
    if (e < NGRAPH * 64) d_g64[e] = 0.f;  // zero pooled accum (free ride)
    if (e < NEDGES / 4) {
        int4 s = src4[e];
        int4 d = dst4[e];
        int4 p = reinterpret_cast<const int4*>(d_posin)[e];
        d_col[d_rowptr[d.x] + p.x] = s.x;
        d_col[d_rowptr[d.y] + p.y] = s.y;
        d_col[d_rowptr[d.z] + p.z] = s.z;
        d_col[d_rowptr[d.w] + p.w] = s.w;
    }
}

// ---------------- GEMM1: Y1 = dinv * (x @ W1), tensor cores ----------------
__global__ __launch_bounds__(256) void k_mma1(const float* __restrict__ x,
                                              const float* __restrict__ W) {
    __shared__ __half Asm[128][136];
    __shared__ __half Wsm[128][40];
    int tid = threadIdx.x;

    for (int i = tid; i < 128 * 32; i += 256)
        Wsm[i >> 5][i & 31] = __float2half(W[i]);

    int row0 = blockIdx.x * 128;
    for (int i = tid; i < 128 * 32; i += 256) {
        int r = i >> 5, c4 = i & 31;
        int gr = row0 + r;
        float4 v = (gr < NNODES)
            ? *reinterpret_cast<const float4*>(&x[(size_t)gr * 128 + c4 * 4])
            : make_float4(0.f, 0.f, 0.f, 0.f);
        __half2 h0 = __floats2half2_rn(v.x, v.y);
        __half2 h1 = __floats2half2_rn(v.z, v.w);
        uint2 pk;
        pk.x = *reinterpret_cast<uint32_t*>(&h0);
        pk.y = *reinterpret_cast<uint32_t*>(&h1);
        *reinterpret_cast<uint2*>(&Asm[r][c4 * 4]) = pk;
    }
    __syncthreads();

    int warp = tid >> 5, lane = tid & 31;
    float acc[4][4];
#pragma unroll
    for (int i = 0; i < 4; i++)
#pragma unroll
        for (int j = 0; j < 4; j++) acc[i][j] = 0.f;

    uint32_t aBase = smem_u32(&Asm[warp * 16 + (lane & 15)][(lane >> 4) * 8]);
#pragma unroll
    for (int ks = 0; ks < 8; ks++) {
        uint32_t a[4];
        ldm_x4(a[0], a[1], a[2], a[3], aBase + ks * 32);
#pragma unroll
        for (int nb = 0; nb < 2; nb++) {
            uint32_t b[4];
            uint32_t bAddr = smem_u32(&Wsm[ks * 16 + (lane & 15)][nb * 16 + (lane >> 4) * 8]);
            ldm_x4t(b[0], b[1], b[2], b[3], bAddr);
            mma16816(acc[nb * 2 + 0], a, b[0], b[1]);
            mma16816(acc[nb * 2 + 1], a, b[2], b[3]);
        }
    }

    int g = lane >> 2, t = lane & 3;
    int n0 = row0 + warp * 16 + g;
    int n1 = n0 + 8;
    float dv0 = (n0 < NNODES) ? d_dinv[n0] : 0.f;
    float dv1 = (n1 < NNODES) ? d_dinv[n1] : 0.f;
#pragma unroll
    for (int nt = 0; nt < 4; nt++) {
        int col = nt * 8 + t * 2;
        if (n0 < NNODES)
            *reinterpret_cast<__half2*>(&d_hA[(size_t)n0 * 32 + col]) =
                __floats2half2_rn(acc[nt][0] * dv0, acc[nt][1] * dv0);
        if (n1 < NNODES)
            *reinterpret_cast<__half2*>(&d_hA[(size_t)n1 * 32 + col]) =
                __floats2half2_rn(acc[nt][2] * dv1, acc[nt][3] * dv1);
    }
}

// ---------------- agg1: P1 = d*relu(d*sum + b1), hA -> hB, F=32 -----------
__launch_bounds__(256)
__global__ void k_agg1(const float* __restrict__ bias) {
    const uint4* __restrict__ Y = (const uint4*)d_hA;
    uint4* __restrict__ O = (uint4*)d_hB;

    int warp = (blockIdx.x * 256 + threadIdx.x) >> 5;
    int lane = threadIdx.x & 31;
    int g = lane >> 2;   // 8 nodes per warp
    int fl = lane & 3;   // 4 lanes per node (16B each)
    int node = warp * 8 + g;
    if (node >= NNODES) return;

    float acc[8];
#pragma unroll
    for (int q = 0; q < 8; q++) acc[q] = 0.f;
    acc8(acc, __ldg(&Y[(size_t)node * 4 + fl]));

    int s = __ldg(&d_rowptr[node]);
    int e = __ldg(&d_rowptr[node + 1]);
    int j = s;
    // 4-wide software pipeline: 4 independent col loads, then 4 feature loads
    for (; j + 3 < e; j += 4) {
        int c0 = __ldg(&d_col[j + 0]);
        int c1 = __ldg(&d_col[j + 1]);
        int c2 = __ldg(&d_col[j + 2]);
        int c3 = __ldg(&d_col[j + 3]);
        uint4 v0 = __ldg(&Y[(size_t)c0 * 4 + fl]);
        uint4 v1 = __ldg(&Y[(size_t)c1 * 4 + fl]);
        uint4 v2 = __ldg(&Y[(size_t)c2 * 4 + fl]);
        uint4 v3 = __ldg(&Y[(size_t)c3 * 4 + fl]);
        acc8(acc, v0); acc8(acc, v1); acc8(acc, v2); acc8(acc, v3);
    }
    for (; j < e; j++) {
        int c = __ldg(&d_col[j]);
        acc8(acc, __ldg(&Y[(size_t)c * 4 + fl]));
    }

    float d = d_dinv[node];
    __half2 hv[4];
#pragma unroll
    for (int q = 0; q < 4; q++) {
        float t0 = acc[q * 2 + 0] * d + bias[fl * 8 + q * 2];
        float t1 = acc[q * 2 + 1] * d + bias[fl * 8 + q * 2 + 1];
        t0 = fmaxf(t0, 0.f) * d;
        t1 = fmaxf(t1, 0.f) * d;
        hv[q] = __floats2half2_rn(t0, t1);
    }
    O[(size_t)node * 4 + fl] = *reinterpret_cast<uint4*>(hv);
}

// ---------------- fused agg2 + GEMM2 --------------------------------------
__global__ __launch_bounds__(256) void k_agg2mma2(const float* __restrict__ W,
                                                  const float* __restrict__ bias) {
    __shared__ __half Asm[128][40];
    __shared__ __half Wsm[32][72];
    __shared__ float bsm[64];
    int tid = threadIdx.x;

    for (int i = tid; i < 32 * 64; i += 256)
        Wsm[i >> 6][i & 63] = __float2half(W[i]);
    if (tid < 64) bsm[tid] = bias[tid];

    const uint4* __restrict__ Y = (const uint4*)d_hB;  // P1, 4 uint4/row
    int row0 = blockIdx.x * 128;
    int warp = tid >> 5, lane = tid & 31;

    // phase 1: gather (8 nodes/warp, 4 lanes/node), 4-wide pipelined
    {
        int g = lane >> 2, fl = lane & 3;
#pragma unroll
        for (int pass = 0; pass < 2; pass++) {
            int r = pass * 64 + warp * 8 + g;
            int node = row0 + r;
            float acc[8];
#pragma unroll
            for (int q = 0; q < 8; q++) acc[q] = 0.f;
            if (node < NNODES) {
                acc8(acc, __ldg(&Y[(size_t)node * 4 + fl]));
                int s = __ldg(&d_rowptr[node]);
                int e = __ldg(&d_rowptr[node + 1]);
                int j = s;
                for (; j + 3 < e; j += 4) {
                    int c0 = __ldg(&d_col[j + 0]);
                    int c1 = __ldg(&d_col[j + 1]);
                    int c2 = __ldg(&d_col[j + 2]);
                    int c3 = __ldg(&d_col[j + 3]);
                    uint4 v0 = __ldg(&Y[(size_t)c0 * 4 + fl]);
                    uint4 v1 = __ldg(&Y[(size_t)c1 * 4 + fl]);
                    uint4 v2 = __ldg(&Y[(size_t)c2 * 4 + fl]);
                    uint4 v3 = __ldg(&Y[(size_t)c3 * 4 + fl]);
                    acc8(acc, v0); acc8(acc, v1); acc8(acc, v2); acc8(acc, v3);
                }
                for (; j < e; j++) {
                    int c = __ldg(&d_col[j]);
                    acc8(acc, __ldg(&Y[(size_t)c * 4 + fl]));
                }
                float d = d_dinv[node];
#pragma unroll
                for (int q = 0; q < 8; q++) acc[q] *= d;
            }
            __half2 hv[4];
#pragma unroll
            for (int q = 0; q < 4; q++)
                hv[q] = __floats2half2_rn(acc[q * 2], acc[q * 2 + 1]);
            *reinterpret_cast<uint4*>(&Asm[r][fl * 8]) = *reinterpret_cast<uint4*>(hv);
        }
    }
    __syncthreads();

    // phase 2: tensor-core GEMM
    float accm[8][4];
#pragma unroll
    for (int i = 0; i < 8; i++)
#pragma unroll
        for (int j = 0; j < 4; j++) accm[i][j] = 0.f;

    uint32_t aBase = smem_u32(&Asm[warp * 16 + (lane & 15)][(lane >> 4) * 8]);
#pragma unroll
    for (int ks = 0; ks < 2; ks++) {
        uint32_t a[4];
        ldm_x4(a[0], a[1], a[2], a[3], aBase + ks * 32);
#pragma unroll
        for (int nb = 0; nb < 4; nb++) {
            uint32_t b[4];
            uint32_t bAddr = smem_u32(&Wsm[ks * 16 + (lane & 15)][nb * 16 + (lane >> 4) * 8]);
            ldm_x4t(b[0], b[1], b[2], b[3], bAddr);
            mma16816(accm[nb * 2 + 0], a, b[0], b[1]);
            mma16816(accm[nb * 2 + 1], a, b[2], b[3]);
        }
    }

    int g2 = lane >> 2, t2 = lane & 3;
    int n0 = row0 + warp * 16 + g2;
    int n1 = n0 + 8;
    float dv0 = (n0 < NNODES) ? d_dinv[n0] : 0.f;
    float dv1 = (n1 < NNODES) ? d_dinv[n1] : 0.f;
#pragma unroll
    for (int nt = 0; nt < 8; nt++) {
        int col = nt * 8 + t2 * 2;
        float b0 = bsm[col], b1 = bsm[col + 1];
        if (n0 < NNODES) {
            float t0 = fmaxf(accm[nt][0] + b0, 0.f) * dv0;
            float t1 = fmaxf(accm[nt][1] + b1, 0.f) * dv0;
            *reinterpret_cast<__half2*>(&d_hA[(size_t)n0 * 64 + col]) = __floats2half2_rn(t0, t1);
        }
        if (n1 < NNODES) {
            float t0 = fmaxf(accm[nt][2] + b0, 0.f) * dv1;
            float t1 = fmaxf(accm[nt][3] + b1, 0.f) * dv1;
            *reinterpret_cast<__half2*>(&d_hA[(size_t)n1 * 64 + col]) = __floats2half2_rn(t0, t1);
        }
    }
}

// ---------------- agg3 fused with global_add_pool --------------------------
__launch_bounds__(256)
__global__ void k_agg64pool(const int* __restrict__ batch) {
    const uint4* __restrict__ Y = (const uint4*)d_hA;  // P2, 8 uint4/row
    __shared__ float red[8][64];
    __shared__ int bsh[8];

    int tid = threadIdx.x;
    int warpid = tid >> 5;
    int warp = (blockIdx.x * 256 + tid) >> 5;
    int lane = tid & 31;
    int g = lane >> 3;   // 4 nodes per warp
    int fl = lane & 7;   // 8 lanes per node
    int node = warp * 4 + g;   // exact tiling (100000 % 4 == 0)

    float acc[8];
#pragma unroll
    for (int q = 0; q < 8; q++) acc[q] = 0.f;
    acc8(acc, __ldg(&Y[(size_t)node * 8 + fl]));

    int s = __ldg(&d_rowptr[node]);
    int e = __ldg(&d_rowptr[node + 1]);
    int j = s;
    for (; j + 3 < e; j += 4) {
        int c0 = __ldg(&d_col[j + 0]);
        int c1 = __ldg(&d_col[j + 1]);
        int c2 = __ldg(&d_col[j + 2]);
        int c3 = __ldg(&d_col[j + 3]);
        uint4 v0 = __ldg(&Y[(size_t)c0 * 8 + fl]);
        uint4 v1 = __ldg(&Y[(size_t)c1 * 8 + fl]);
        uint4 v2 = __ldg(&Y[(size_t)c2 * 8 + fl]);
        uint4 v3 = __ldg(&Y[(size_t)c3 * 8 + fl]);
        acc8(acc, v0); acc8(acc, v1); acc8(acc, v2); acc8(acc, v3);
    }
    for (; j < e; j++) {
        int c = __ldg(&d_col[j]);
        acc8(acc, __ldg(&Y[(size_t)c * 8 + fl]));
    }
    float d = d_dinv[node];
#pragma unroll
    for (int q = 0; q < 8; q++) acc[q] *= d;

    int b = __ldg(&batch[node]);
    unsigned m = 0xffffffffu;
    // both shuffles unconditional (no && short-circuit -> no divergent-shfl hang)
    int b8  = __shfl_xor_sync(m, b, 8);
    int b16 = __shfl_xor_sync(m, b, 16);
    bool uni = (b == b8) & (b == b16);
    bool wuni = __all_sync(m, uni);

    if (lane == 0) bsh[warpid] = wuni ? b : -1;
    __syncthreads();
    int b0 = bsh[0];
    bool blockuni = (b0 >= 0);
#pragma unroll
    for (int w = 1; w < 8; w++) blockuni &= (bsh[w] == b0);

    if (blockuni) {
#pragma unroll
        for (int q = 0; q < 8; q++) {
            acc[q] += __shfl_xor_sync(m, acc[q], 8);
            acc[q] += __shfl_xor_sync(m, acc[q], 16);
        }
        if (lane < 8) {
#pragma unroll
            for (int q = 0; q < 8; q++) red[warpid][lane * 8 + q] = acc[q];
        }
    }
    __syncthreads();
    if (blockuni) {
        if (tid < 64) {
            float sum = 0.f;
#pragma unroll
            for (int w = 0; w < 8; w++) sum += red[w][tid];
            atomicAdd(&d_g64[b0 * 64 + tid], sum);
        }
    } else {
        if (wuni) {
#pragma unroll
            for (int q = 0; q < 8; q++) {
                acc[q] += __shfl_xor_sync(m, acc[q], 8);
                acc[q] += __shfl_xor_sync(m, acc[q], 16);
            }
            if (lane < 8) {
                float* gp = &d_g64[b * 64 + fl * 8];
#pragma unroll
                for (int q = 0; q < 8; q++) atomicAdd(&gp[q], acc[q]);
            }
        } else {
            float* gp = &d_g64[b * 64 + fl * 8];
#pragma unroll
            for (int q = 0; q < 8; q++) atomicAdd(&gp[q], acc[q]);
        }
    }
}

// ---------------- GEMM3 (folded) + MLP head + log_softmax ----------------
__global__ void k_mlp(const int* __restrict__ batch,
                      const float* __restrict__ W3, const float* __restrict__ b3,
                      const float* __restrict__ Wl1, const float* __restrict__ bl1,
                      const float* __restrict__ Wl2, const float* __restrict__ bl2,
                      float* __restrict__ out) {
    __shared__ float g[64];
    __shared__ float h3[128];
    __shared__ float hid[64];
    __shared__ float o[10];
    __shared__ int cnt_s;
    int b = blockIdx.x, t = threadIdx.x;
    if (t < 64) g[t] = d_g64[b * 64 + t];
    if (t == 0) {
        int lo = 0, hi = NNODES;
        while (lo < hi) { int m = (lo + hi) >> 1; if (batch[m] < b) lo = m + 1; else hi = m; }
        int lb = lo;
        hi = NNODES;
        while (lo < hi) { int m = (lo + hi) >> 1; if (batch[m] <= b) lo = m + 1; else hi = m; }
        cnt_s = lo - lb;
    }
    __syncthreads();
    float nb = (float)cnt_s;
    {
        float a = nb * b3[t];
        for (int k = 0; k < 64; k++) a += g[k] * W3[k * 128 + t];
        h3[t] = a;
    }
    __syncthreads();
    if (t < 64) {
        float a = bl1[t];
        for (int k = 0; k < 128; k++) a += h3[k] * Wl1[k * 64 + t];
        hid[t] = fmaxf(a, 0.f);
    }
    __syncthreads();
    if (t < 10) {
        float a = bl2[t];
        for (int k = 0; k < 64; k++) a += hid[k] * Wl2[k * 10 + t];
        o[t] = a;
    }
    __syncthreads();
    if (t == 0) {
        float m = -INFINITY;
        for (int i = 0; i < 10; i++) m = fmaxf(m, o[i]);
        float s = 0.f;
        for (int i = 0; i < 10; i++) s += expf(o[i] - m);
        float l = m + logf(s);
        for (int i = 0; i < 10; i++) out[b * 10 + i] = o[i] - l;
    }
}

// ---------------- launch ----------------
extern "C" void kernel_launch(void* const* d_in, const int* in_sizes, int n_in,
                              void* d_out, int out_size) {
    const float* x     = (const float*)d_in[0];
    const int*   ei    = (const int*)d_in[1];
    const int*   batch = (const int*)d_in[2];
    const float* W1  = (const float*)d_in[3];
    const float* b1  = (const float*)d_in[4];
    const float* W2  = (const float*)d_in[5];
    const float* b2  = (const float*)d_in[6];
    const float* W3  = (const float*)d_in[7];
    const float* b3  = (const float*)d_in[8];
    const float* Wl1 = (const float*)d_in[9];
    const float* bl1 = (const float*)d_in[10];
    const float* Wl2 = (const float*)d_in[11];
    const float* bl2 = (const float*)d_in[12];
    float* out = (float*)d_out;

    const int4* src4 = (const int4*)ei;
    const int4* dst4 = (const int4*)(ei + NEDGES);

    const int NBLK_SCAN = (NNODES + 511) / 512;                // 196
    const int E4BLK = (NEDGES / 4 + 255) / 256;                // 1563
    const int AGG32_BLK = ((NNODES + 7) / 8 * 32 + 255) / 256; // 1563
    const int AGG64_BLK = (NNODES / 4 * 32) / 256;             // 3125 (exact)
    const int MMABLK = (NNODES + 127) / 128;                   // 782

    // CSR build (deg zeroed by previous call's k_scan3 / module-load init)
    k_degpos<<<E4BLK, 256>>>(dst4);
    k_scan1<<<NBLK_SCAN, 512>>>();
    k_scan3<<<NBLK_SCAN, 512>>>(NBLK_SCAN);
    k_scatter<<<E4BLK, 256>>>(src4, dst4);

    // L1: Y1 = d*(x@W1)                      x -> hA   (tensor cores)
    k_mma1<<<MMABLK, 256>>>(x, W1);
    // agg1: P1 = d*relu(d*sum + b1)          hA -> hB
    k_agg1<<<AGG32_BLK, 256>>>(b1);
    // fused agg2+L2: P2 = d*relu((d*sum)@W2+b2)  hB -> hA
    k_agg2mma2<<<MMABLK, 256>>>(W2, b2);
    // agg3 + pool: g64 += d*sum(P2)          hA -> d_g64
    k_agg64pool<<<AGG64_BLK, 256>>>(batch);

    // folded GEMM3 + MLP head
    k_mlp<<<NGRAPH, 128>>>(batch, W3, b3, Wl1, bl1, Wl2, bl2, out);
}

// round 14
// speedup vs baseline: 1.5120x; 1.0098x over previous
#include <cuda_runtime.h>
#include <cuda_fp16.h>
#include <stdint.h>
#include <math.h>

// Problem-fixed shapes
#define NNODES 100000
#define NEDGES 1600000
#define NGRAPH 512

// ---------------- scratch (device globals; no allocation) ----------------
__device__ int    d_deg[NNODES];          // zero-init at load; restored to 0 each call
__device__ int    d_rowptr[NNODES + 1];
__device__ int    d_posin[NEDGES];
__device__ int    d_col[NEDGES];
__device__ float  d_dinv[NNODES];
__device__ __half d_hA[(size_t)NNODES * 64];
__device__ __half d_hB[(size_t)NNODES * 64];
__device__ float  d_g64[NGRAPH * 64];
__device__ int    d_bsum[256];

// ---------------- mma helpers ----------------
__device__ __forceinline__ uint32_t smem_u32(const void* p) {
    return (uint32_t)__cvta_generic_to_shared(p);
}
__device__ __forceinline__ void ldm_x4(uint32_t& r0, uint32_t& r1,
                                       uint32_t& r2, uint32_t& r3, uint32_t a) {
    asm volatile("ldmatrix.sync.aligned.m8n8.x4.shared.b16 {%0,%1,%2,%3}, [%4];"
                 : "=r"(r0), "=r"(r1), "=r"(r2), "=r"(r3) : "r"(a));
}
__device__ __forceinline__ void ldm_x4t(uint32_t& r0, uint32_t& r1,
                                        uint32_t& r2, uint32_t& r3, uint32_t a) {
    asm volatile("ldmatrix.sync.aligned.m8n8.x4.trans.shared.b16 {%0,%1,%2,%3}, [%4];"
                 : "=r"(r0), "=r"(r1), "=r"(r2), "=r"(r3) : "r"(a));
}
__device__ __forceinline__ void mma16816(float* c, const uint32_t* a,
                                         uint32_t b0, uint32_t b1) {
    asm volatile(
        "mma.sync.aligned.m16n8k16.row.col.f32.f16.f16.f32 "
        "{%0,%1,%2,%3}, {%4,%5,%6,%7}, {%8,%9}, {%0,%1,%2,%3};"
        : "+f"(c[0]), "+f"(c[1]), "+f"(c[2]), "+f"(c[3])
        : "r"(a[0]), "r"(a[1]), "r"(a[2]), "r"(a[3]), "r"(b0), "r"(b1));
}

// accumulate a uint4 of 8 halves into 8 fp32 accumulators
__device__ __forceinline__ void acc8(float* acc, uint4 v) {
    const __half2* h = reinterpret_cast<const __half2*>(&v);
#pragma unroll
    for (int q = 0; q < 4; q++) {
        float2 f = __half22float2(h[q]);
        acc[q * 2 + 0] += f.x;
        acc[q * 2 + 1] += f.y;
    }
}

// ---------------- CSR build ----------------
__global__ void k_degpos(const int4* __restrict__ dst4) {
    int e = blockIdx.x * blockDim.x + threadIdx.x;
    if (e < NEDGES / 4) {
        int4 d = dst4[e];
        int4 p;
        p.x = atomicAdd(&d_deg[d.x], 1);
        p.y = atomicAdd(&d_deg[d.y], 1);
        p.z = atomicAdd(&d_deg[d.z], 1);
        p.w = atomicAdd(&d_deg[d.w], 1);
        reinterpret_cast<int4*>(d_posin)[e] = p;
    }
}

__global__ void k_scan1() {
    __shared__ int s[512];
    int i = blockIdx.x * 512 + threadIdx.x;
    int v = (i < NNODES) ? d_deg[i] : 0;
    s[threadIdx.x] = v;
    __syncthreads();
    for (int off = 1; off < 512; off <<= 1) {
        int t = (threadIdx.x >= off) ? s[threadIdx.x - off] : 0;
        __syncthreads();
        s[threadIdx.x] += t;
        __syncthreads();
    }
    if (i < NNODES) d_rowptr[i] = s[threadIdx.x] - v;
    if (threadIdx.x == 511) d_bsum[blockIdx.x] = s[511];
}

__global__ void k_scan3(int nblk) {
    __shared__ int red[512];
    int t = threadIdx.x;
    red[t] = (t < blockIdx.x) ? d_bsum[t] : 0;
    __syncthreads();
#pragma unroll
    for (int off = 256; off > 0; off >>= 1) {
        if (t < off) red[t] += red[t + off];
        __syncthreads();
    }
    int soff = red[0];
    __syncthreads();
    if (blockIdx.x == (int)gridDim.x - 1) {
        red[t] = (t < nblk) ? d_bsum[t] : 0;
        __syncthreads();
#pragma unroll
        for (int off = 256; off > 0; off >>= 1) {
            if (t < off) red[t] += red[t + off];
            __syncthreads();
        }
        if (t == 0) d_rowptr[NNODES] = red[0];
    }
    int i = blockIdx.x * 512 + t;
    if (i < NNODES) {
        d_rowptr[i] += soff;
        d_dinv[i] = rsqrtf((float)(d_deg[i] + 1));
        d_deg[i] = 0;   // restore invariant for next call
    }
}

// ---------------- fused scatter + GEMM1 (independent: both need only scan3) --
// blocks [0, MMABLK): mma1 path -> Y1 = dinv*(x@W1), x -> hA (tensor cores)
// blocks [MMABLK, MMABLK+E4BLK): atomic-free scatter + g64 zeroing
#define MMABLK_C 782   // (NNODES + 127) / 128
#define E4BLK_C 1563   // (NEDGES/4 + 255) / 256

__global__ __launch_bounds__(256) void k_scatter_mma1(
    const float* __restrict__ x, const float* __restrict__ W,
    const int4* __restrict__ src4, const int4* __restrict__ dst4) {
    __shared__ __half Asm[128][136];
    __shared__ __half Wsm[128][40];
    int tid = threadIdx.x;

    if (blockIdx.x >= MMABLK_C) {
        // ---- scatter path ----
        int e = (blockIdx.x - MMABLK_C) * 256 + tid;
        if (e < NGRAPH * 64) d_g64[e] = 0.f;  // zero pooled accum (free ride)
        if (e < NEDGES / 4) {
            int4 s = src4[e];
            int4 d = dst4[e];
            int4 p = reinterpret_cast<const int4*>(d_posin)[e];
            d_col[d_rowptr[d.x] + p.x] = s.x;
            d_col[d_rowptr[d.y] + p.y] = s.y;
            d_col[d_rowptr[d.z] + p.z] = s.z;
            d_col[d_rowptr[d.w] + p.w] = s.w;
        }
        return;
    }

    // ---- mma1 path ----
    for (int i = tid; i < 128 * 32; i += 256)
        Wsm[i >> 5][i & 31] = __float2half(W[i]);

    int row0 = blockIdx.x * 128;
    for (int i = tid; i < 128 * 32; i += 256) {
        int r = i >> 5, c4 = i & 31;
        int gr = row0 + r;
        float4 v = (gr < NNODES)
            ? *reinterpret_cast<const float4*>(&x[(size_t)gr * 128 + c4 * 4])
            : make_float4(0.f, 0.f, 0.f, 0.f);
        __half2 h0 = __floats2half2_rn(v.x, v.y);
        __half2 h1 = __floats2half2_rn(v.z, v.w);
        uint2 pk;
        pk.x = *reinterpret_cast<uint32_t*>(&h0);
        pk.y = *reinterpret_cast<uint32_t*>(&h1);
        *reinterpret_cast<uint2*>(&Asm[r][c4 * 4]) = pk;
    }
    __syncthreads();

    int warp = tid >> 5, lane = tid & 31;
    float acc[4][4];
#pragma unroll
    for (int i = 0; i < 4; i++)
#pragma unroll
        for (int j = 0; j < 4; j++) acc[i][j] = 0.f;

    uint32_t aBase = smem_u32(&Asm[warp * 16 + (lane & 15)][(lane >> 4) * 8]);
#pragma unroll
    for (int ks = 0; ks < 8; ks++) {
        uint32_t a[4];
        ldm_x4(a[0], a[1], a[2], a[3], aBase + ks * 32);
#pragma unroll
        for (int nb = 0; nb < 2; nb++) {
            uint32_t b[4];
            uint32_t bAddr = smem_u32(&Wsm[ks * 16 + (lane & 15)][nb * 16 + (lane >> 4) * 8]);
            ldm_x4t(b[0], b[1], b[2], b[3], bAddr);
            mma16816(acc[nb * 2 + 0], a, b[0], b[1]);
            mma16816(acc[nb * 2 + 1], a, b[2], b[3]);
        }
    }

    int g = lane >> 2, t = lane & 3;
    int n0 = row0 + warp * 16 + g;
    int n1 = n0 + 8;
    float dv0 = (n0 < NNODES) ? d_dinv[n0] : 0.f;
    float dv1 = (n1 < NNODES) ? d_dinv[n1] : 0.f;
#pragma unroll
    for (int nt = 0; nt < 4; nt++) {
        int col = nt * 8 + t * 2;
        if (n0 < NNODES)
            *reinterpret_cast<__half2*>(&d_hA[(size_t)n0 * 32 + col]) =
                __floats2half2_rn(acc[nt][0] * dv0, acc[nt][1] * dv0);
        if (n1 < NNODES)
            *reinterpret_cast<__half2*>(&d_hA[(size_t)n1 * 32 + col]) =
                __floats2half2_rn(acc[nt][2] * dv1, acc[nt][3] * dv1);
    }
}

// ---------------- agg1: P1 = d*relu(d*sum + b1), hA -> hB, F=32 -----------
__launch_bounds__(256)
__global__ void k_agg1(const float* __restrict__ bias) {
    const uint4* __restrict__ Y = (const uint4*)d_hA;
    uint4* __restrict__ O = (uint4*)d_hB;

    int warp = (blockIdx.x * 256 + threadIdx.x) >> 5;
    int lane = threadIdx.x & 31;
    int g = lane >> 2;   // 8 nodes per warp
    int fl = lane & 3;   // 4 lanes per node (16B each)
    int node = warp * 8 + g;
    if (node >= NNODES) return;

    float acc[8];
#pragma unroll
    for (int q = 0; q < 8; q++) acc[q] = 0.f;
    acc8(acc, __ldg(&Y[(size_t)node * 4 + fl]));

    int s = __ldg(&d_rowptr[node]);
    int e = __ldg(&d_rowptr[node + 1]);
    int j = s;
    for (; j + 3 < e; j += 4) {
        int c0 = __ldg(&d_col[j + 0]);
        int c1 = __ldg(&d_col[j + 1]);
        int c2 = __ldg(&d_col[j + 2]);
        int c3 = __ldg(&d_col[j + 3]);
        uint4 v0 = __ldg(&Y[(size_t)c0 * 4 + fl]);
        uint4 v1 = __ldg(&Y[(size_t)c1 * 4 + fl]);
        uint4 v2 = __ldg(&Y[(size_t)c2 * 4 + fl]);
        uint4 v3 = __ldg(&Y[(size_t)c3 * 4 + fl]);
        acc8(acc, v0); acc8(acc, v1); acc8(acc, v2); acc8(acc, v3);
    }
    for (; j < e; j++) {
        int c = __ldg(&d_col[j]);
        acc8(acc, __ldg(&Y[(size_t)c * 4 + fl]));
    }

    float d = d_dinv[node];
    __half2 hv[4];
#pragma unroll
    for (int q = 0; q < 4; q++) {
        float t0 = acc[q * 2 + 0] * d + bias[fl * 8 + q * 2];
        float t1 = acc[q * 2 + 1] * d + bias[fl * 8 + q * 2 + 1];
        t0 = fmaxf(t0, 0.f) * d;
        t1 = fmaxf(t1, 0.f) * d;
        hv[q] = __floats2half2_rn(t0, t1);
    }
    O[(size_t)node * 4 + fl] = *reinterpret_cast<uint4*>(hv);
}

// ---------------- fused agg2 + GEMM2 --------------------------------------
__global__ __launch_bounds__(256) void k_agg2mma2(const float* __restrict__ W,
                                                  const float* __restrict__ bias) {
    __shared__ __half Asm[128][40];
    __shared__ __half Wsm[32][72];
    __shared__ float bsm[64];
    int tid = threadIdx.x;

    for (int i = tid; i < 32 * 64; i += 256)
        Wsm[i >> 6][i & 63] = __float2half(W[i]);
    if (tid < 64) bsm[tid] = bias[tid];

    const uint4* __restrict__ Y = (const uint4*)d_hB;  // P1, 4 uint4/row
    int row0 = blockIdx.x * 128;
    int warp = tid >> 5, lane = tid & 31;

    // phase 1: gather (8 nodes/warp, 4 lanes/node)
    {
        int g = lane >> 2, fl = lane & 3;
#pragma unroll
        for (int pass = 0; pass < 2; pass++) {
            int r = pass * 64 + warp * 8 + g;
            int node = row0 + r;
            float acc[8];
#pragma unroll
            for (int q = 0; q < 8; q++) acc[q] = 0.f;
            if (node < NNODES) {
                acc8(acc, __ldg(&Y[(size_t)node * 4 + fl]));
                int s = __ldg(&d_rowptr[node]);
                int e = __ldg(&d_rowptr[node + 1]);
                int j = s;
                for (; j + 3 < e; j += 4) {
                    int c0 = __ldg(&d_col[j + 0]);
                    int c1 = __ldg(&d_col[j + 1]);
                    int c2 = __ldg(&d_col[j + 2]);
                    int c3 = __ldg(&d_col[j + 3]);
                    uint4 v0 = __ldg(&Y[(size_t)c0 * 4 + fl]);
                    uint4 v1 = __ldg(&Y[(size_t)c1 * 4 + fl]);
                    uint4 v2 = __ldg(&Y[(size_t)c2 * 4 + fl]);
                    uint4 v3 = __ldg(&Y[(size_t)c3 * 4 + fl]);
                    acc8(acc, v0); acc8(acc, v1); acc8(acc, v2); acc8(acc, v3);
                }
                for (; j < e; j++) {
                    int c = __ldg(&d_col[j]);
                    acc8(acc, __ldg(&Y[(size_t)c * 4 + fl]));
                }
                float d = d_dinv[node];
#pragma unroll
                for (int q = 0; q < 8; q++) acc[q] *= d;
            }
            __half2 hv[4];
#pragma unroll
            for (int q = 0; q < 4; q++)
                hv[q] = __floats2half2_rn(acc[q * 2], acc[q * 2 + 1]);
            *reinterpret_cast<uint4*>(&Asm[r][fl * 8]) = *reinterpret_cast<uint4*>(hv);
        }
    }
    __syncthreads();

    // phase 2: tensor-core GEMM
    float accm[8][4];
#pragma unroll
    for (int i = 0; i < 8; i++)
#pragma unroll
        for (int j = 0; j < 4; j++) accm[i][j] = 0.f;

    uint32_t aBase = smem_u32(&Asm[warp * 16 + (lane & 15)][(lane >> 4) * 8]);
#pragma unroll
    for (int ks = 0; ks < 2; ks++) {
        uint32_t a[4];
        ldm_x4(a[0], a[1], a[2], a[3], aBase + ks * 32);
#pragma unroll
        for (int nb = 0; nb < 4; nb++) {
            uint32_t b[4];
            uint32_t bAddr = smem_u32(&Wsm[ks * 16 + (lane & 15)][nb * 16 + (lane >> 4) * 8]);
            ldm_x4t(b[0], b[1], b[2], b[3], bAddr);
            mma16816(accm[nb * 2 + 0], a, b[0], b[1]);
            mma16816(accm[nb * 2 + 1], a, b[2], b[3]);
        }
    }

    int g2 = lane >> 2, t2 = lane & 3;
    int n0 = row0 + warp * 16 + g2;
    int n1 = n0 + 8;
    float dv0 = (n0 < NNODES) ? d_dinv[n0] : 0.f;
    float dv1 = (n1 < NNODES) ? d_dinv[n1] : 0.f;
#pragma unroll
    for (int nt = 0; nt < 8; nt++) {
        int col = nt * 8 + t2 * 2;
        float b0 = bsm[col], b1 = bsm[col + 1];
        if (n0 < NNODES) {
            float t0 = fmaxf(accm[nt][0] + b0, 0.f) * dv0;
            float t1 = fmaxf(accm[nt][1] + b1, 0.f) * dv0;
            *reinterpret_cast<__half2*>(&d_hA[(size_t)n0 * 64 + col]) = __floats2half2_rn(t0, t1);
        }
        if (n1 < NNODES) {
            float t0 = fmaxf(accm[nt][2] + b0, 0.f) * dv1;
            float t1 = fmaxf(accm[nt][3] + b1, 0.f) * dv1;
            *reinterpret_cast<__half2*>(&d_hA[(size_t)n1 * 64 + col]) = __floats2half2_rn(t0, t1);
        }
    }
}

// ---------------- agg3 fused with global_add_pool --------------------------
__launch_bounds__(256)
__global__ void k_agg64pool(const int* __restrict__ batch) {
    const uint4* __restrict__ Y = (const uint4*)d_hA;  // P2, 8 uint4/row
    __shared__ float red[8][64];
    __shared__ int bsh[8];

    int tid = threadIdx.x;
    int warpid = tid >> 5;
    int warp = (blockIdx.x * 256 + tid) >> 5;
    int lane = tid & 31;
    int g = lane >> 3;   // 4 nodes per warp
    int fl = lane & 7;   // 8 lanes per node
    int node = warp * 4 + g;   // exact tiling (100000 % 4 == 0)

    float acc[8];
#pragma unroll
    for (int q = 0; q < 8; q++) acc[q] = 0.f;
    acc8(acc, __ldg(&Y[(size_t)node * 8 + fl]));

    int s = __ldg(&d_rowptr[node]);
    int e = __ldg(&d_rowptr[node + 1]);
    int j = s;
    for (; j + 3 < e; j += 4) {
        int c0 = __ldg(&d_col[j + 0]);
        int c1 = __ldg(&d_col[j + 1]);
        int c2 = __ldg(&d_col[j + 2]);
        int c3 = __ldg(&d_col[j + 3]);
        uint4 v0 = __ldg(&Y[(size_t)c0 * 8 + fl]);
        uint4 v1 = __ldg(&Y[(size_t)c1 * 8 + fl]);
        uint4 v2 = __ldg(&Y[(size_t)c2 * 8 + fl]);
        uint4 v3 = __ldg(&Y[(size_t)c3 * 8 + fl]);
        acc8(acc, v0); acc8(acc, v1); acc8(acc, v2); acc8(acc, v3);
    }
    for (; j < e; j++) {
        int c = __ldg(&d_col[j]);
        acc8(acc, __ldg(&Y[(size_t)c * 8 + fl]));
    }
    float d = d_dinv[node];
#pragma unroll
    for (int q = 0; q < 8; q++) acc[q] *= d;

    int b = __ldg(&batch[node]);
    unsigned m = 0xffffffffu;
    // both shuffles unconditional (no && short-circuit -> no divergent-shfl hang)
    int b8  = __shfl_xor_sync(m, b, 8);
    int b16 = __shfl_xor_sync(m, b, 16);
    bool uni = (b == b8) & (b == b16);
    bool wuni = __all_sync(m, uni);

    if (lane == 0) bsh[warpid] = wuni ? b : -1;
    __syncthreads();
    int b0 = bsh[0];
    bool blockuni = (b0 >= 0);
#pragma unroll
    for (int w = 1; w < 8; w++) blockuni &= (bsh[w] == b0);

    if (blockuni) {
#pragma unroll
        for (int q = 0; q < 8; q++) {
            acc[q] += __shfl_xor_sync(m, acc[q], 8);
            acc[q] += __shfl_xor_sync(m, acc[q], 16);
        }
        if (lane < 8) {
#pragma unroll
            for (int q = 0; q < 8; q++) red[warpid][lane * 8 + q] = acc[q];
        }
    }
    __syncthreads();
    if (blockuni) {
        if (tid < 64) {
            float sum = 0.f;
#pragma unroll
            for (int w = 0; w < 8; w++) sum += red[w][tid];
            atomicAdd(&d_g64[b0 * 64 + tid], sum);
        }
    } else {
        if (wuni) {
#pragma unroll
            for (int q = 0; q < 8; q++) {
                acc[q] += __shfl_xor_sync(m, acc[q], 8);
                acc[q] += __shfl_xor_sync(m, acc[q], 16);
            }
            if (lane < 8) {
                float* gp = &d_g64[b * 64 + fl * 8];
#pragma unroll
                for (int q = 0; q < 8; q++) atomicAdd(&gp[q], acc[q]);
            }
        } else {
            float* gp = &d_g64[b * 64 + fl * 8];
#pragma unroll
            for (int q = 0; q < 8; q++) atomicAdd(&gp[q], acc[q]);
        }
    }
}

// ---------------- GEMM3 (folded) + MLP head + log_softmax ----------------
__global__ void k_mlp(const int* __restrict__ batch,
                      const float* __restrict__ W3, const float* __restrict__ b3,
                      const float* __restrict__ Wl1, const float* __restrict__ bl1,
                      const float* __restrict__ Wl2, const float* __restrict__ bl2,
                      float* __restrict__ out) {
    __shared__ float g[64];
    __shared__ float h3[128];
    __shared__ float hid[64];
    __shared__ float o[10];
    __shared__ int cnt_s;
    int b = blockIdx.x, t = threadIdx.x;
    if (t < 64) g[t] = d_g64[b * 64 + t];
    if (t == 0) {
        int lo = 0, hi = NNODES;
        while (lo < hi) { int m = (lo + hi) >> 1; if (batch[m] < b) lo = m + 1; else hi = m; }
        int lb = lo;
        hi = NNODES;
        while (lo < hi) { int m = (lo + hi) >> 1; if (batch[m] <= b) lo = m + 1; else hi = m; }
        cnt_s = lo - lb;
    }
    __syncthreads();
    float nb = (float)cnt_s;
    {
        float a = nb * b3[t];
        for (int k = 0; k < 64; k++) a += g[k] * W3[k * 128 + t];
        h3[t] = a;
    }
    __syncthreads();
    if (t < 64) {
        float a = bl1[t];
        for (int k = 0; k < 128; k++) a += h3[k] * Wl1[k * 64 + t];
        hid[t] = fmaxf(a, 0.f);
    }
    __syncthreads();
    if (t < 10) {
        float a = bl2[t];
        for (int k = 0; k < 64; k++) a += hid[k] * Wl2[k * 10 + t];
        o[t] = a;
    }
    __syncthreads();
    if (t == 0) {
        float m = -INFINITY;
        for (int i = 0; i < 10; i++) m = fmaxf(m, o[i]);
        float s = 0.f;
        for (int i = 0; i < 10; i++) s += expf(o[i] - m);
        float l = m + logf(s);
        for (int i = 0; i < 10; i++) out[b * 10 + i] = o[i] - l;
    }
}

// ---------------- launch ----------------
extern "C" void kernel_launch(void* const* d_in, const int* in_sizes, int n_in,
                              void* d_out, int out_size) {
    const float* x     = (const float*)d_in[0];
    const int*   ei    = (const int*)d_in[1];
    const int*   batch = (const int*)d_in[2];
    const float* W1  = (const float*)d_in[3];
    const float* b1  = (const float*)d_in[4];
    const float* W2  = (const float*)d_in[5];
    const float* b2  = (const float*)d_in[6];
    const float* W3  = (const float*)d_in[7];
    const float* b3  = (const float*)d_in[8];
    const float* Wl1 = (const float*)d_in[9];
    const float* bl1 = (const float*)d_in[10];
    const float* Wl2 = (const float*)d_in[11];
    const float* bl2 = (const float*)d_in[12];
    float* out = (float*)d_out;

    const int4* src4 = (const int4*)ei;
    const int4* dst4 = (const int4*)(ei + NEDGES);

    const int NBLK_SCAN = (NNODES + 511) / 512;                // 196
    const int E4BLK = (NEDGES / 4 + 255) / 256;                // 1563
    const int AGG32_BLK = ((NNODES + 7) / 8 * 32 + 255) / 256; // 1563
    const int AGG64_BLK = (NNODES / 4 * 32) / 256;             // 3125 (exact)
    const int MMABLK = (NNODES + 127) / 128;                   // 782

    // CSR prefix (deg zeroed by previous call's k_scan3 / module-load init)
    k_degpos<<<E4BLK, 256>>>(dst4);
    k_scan1<<<NBLK_SCAN, 512>>>();
    k_scan3<<<NBLK_SCAN, 512>>>(NBLK_SCAN);

    // fused: scatter (CSR col build) overlapped with L1 GEMM  -> d_col, hA
    k_scatter_mma1<<<MMABLK + E4BLK, 256>>>(x, W1, src4, dst4);

    // agg1: P1 = d*relu(d*sum + b1)          hA -> hB
    k_agg1<<<AGG32_BLK, 256>>>(b1);
    // fused agg2+L2: P2 = d*relu((d*sum)@W2+b2)  hB -> hA
    k_agg2mma2<<<MMABLK, 256>>>(W2, b2);
    // agg3 + pool: g64 += d*sum(P2)          hA -> d_g64
    k_agg64pool<<<AGG64_BLK, 256>>>(batch);

    // folded GEMM3 + MLP head
    k_mlp<<<NGRAPH, 128>>>(batch, W3, b3, Wl1, bl1, Wl2, bl2, out);
}

// round 15
// speedup vs baseline: 1.5841x; 1.0477x over previous
#include <cuda_runtime.h>
#include <cuda_fp16.h>
#include <stdint.h>
#include <math.h>

// Problem-fixed shapes
#define NNODES 100000
#define NEDGES 1600000
#define NGRAPH 512

// ---------------- scratch (device globals; no allocation) ----------------
__device__ int    d_deg[NNODES];          // zero-init at load; restored to 0 each call
__device__ int    d_rowptr[NNODES + 1];
__device__ int    d_posin[NEDGES];
__device__ int    d_col[NEDGES];
__device__ float  d_dinv[NNODES];
__device__ __half d_hA[(size_t)NNODES * 64];
__device__ __half d_hB[(size_t)NNODES * 64];
__device__ float  d_g64[NGRAPH * 64];
__device__ int    d_bsum[256];

// ---------------- mma helpers ----------------
__device__ __forceinline__ uint32_t smem_u32(const void* p) {
    return (uint32_t)__cvta_generic_to_shared(p);
}
__device__ __forceinline__ void ldm_x4(uint32_t& r0, uint32_t& r1,
                                       uint32_t& r2, uint32_t& r3, uint32_t a) {
    asm volatile("ldmatrix.sync.aligned.m8n8.x4.shared.b16 {%0,%1,%2,%3}, [%4];"
                 : "=r"(r0), "=r"(r1), "=r"(r2), "=r"(r3) : "r"(a));
}
__device__ __forceinline__ void ldm_x4t(uint32_t& r0, uint32_t& r1,
                                        uint32_t& r2, uint32_t& r3, uint32_t a) {
    asm volatile("ldmatrix.sync.aligned.m8n8.x4.trans.shared.b16 {%0,%1,%2,%3}, [%4];"
                 : "=r"(r0), "=r"(r1), "=r"(r2), "=r"(r3) : "r"(a));
}
__device__ __forceinline__ void mma16816(float* c, const uint32_t* a,
                                         uint32_t b0, uint32_t b1) {
    asm volatile(
        "mma.sync.aligned.m16n8k16.row.col.f32.f16.f16.f32 "
        "{%0,%1,%2,%3}, {%4,%5,%6,%7}, {%8,%9}, {%0,%1,%2,%3};"
        : "+f"(c[0]), "+f"(c[1]), "+f"(c[2]), "+f"(c[3])
        : "r"(a[0]), "r"(a[1]), "r"(a[2]), "r"(a[3]), "r"(b0), "r"(b1));
}

// accumulate a uint4 of 8 halves into 8 fp32 accumulators
__device__ __forceinline__ void acc8(float* acc, uint4 v) {
    const __half2* h = reinterpret_cast<const __half2*>(&v);
#pragma unroll
    for (int q = 0; q < 4; q++) {
        float2 f = __half22float2(h[q]);
        acc[q * 2 + 0] += f.x;
        acc[q * 2 + 1] += f.y;
    }
}

// ---------------- CSR build ----------------
__global__ void k_degpos(const int4* __restrict__ dst4) {
    int e = blockIdx.x * blockDim.x + threadIdx.x;
    if (e < NEDGES / 4) {
        int4 d = dst4[e];
        int4 p;
        p.x = atomicAdd(&d_deg[d.x], 1);
        p.y = atomicAdd(&d_deg[d.y], 1);
        p.z = atomicAdd(&d_deg[d.z], 1);
        p.w = atomicAdd(&d_deg[d.w], 1);
        reinterpret_cast<int4*>(d_posin)[e] = p;
    }
}

__global__ void k_scan1() {
    __shared__ int s[512];
    int i = blockIdx.x * 512 + threadIdx.x;
    int v = (i < NNODES) ? d_deg[i] : 0;
    s[threadIdx.x] = v;
    __syncthreads();
    for (int off = 1; off < 512; off <<= 1) {
        int t = (threadIdx.x >= off) ? s[threadIdx.x - off] : 0;
        __syncthreads();
        s[threadIdx.x] += t;
        __syncthreads();
    }
    if (i < NNODES) d_rowptr[i] = s[threadIdx.x] - v;
    if (threadIdx.x == 511) d_bsum[blockIdx.x] = s[511];
}

__global__ void k_scan3(int nblk) {
    __shared__ int red[512];
    int t = threadIdx.x;
    red[t] = (t < blockIdx.x) ? d_bsum[t] : 0;
    __syncthreads();
#pragma unroll
    for (int off = 256; off > 0; off >>= 1) {
        if (t < off) red[t] += red[t + off];
        __syncthreads();
    }
    int soff = red[0];
    __syncthreads();
    if (blockIdx.x == (int)gridDim.x - 1) {
        red[t] = (t < nblk) ? d_bsum[t] : 0;
        __syncthreads();
#pragma unroll
        for (int off = 256; off > 0; off >>= 1) {
            if (t < off) red[t] += red[t + off];
            __syncthreads();
        }
        if (t == 0) d_rowptr[NNODES] = red[0];
    }
    int i = blockIdx.x * 512 + t;
    if (i < NNODES) {
        d_rowptr[i] += soff;
        d_dinv[i] = rsqrtf((float)(d_deg[i] + 1));
        d_deg[i] = 0;   // restore invariant for next call
    }
}

// ---------------- fused scatter + GEMM1 (low-smem, 2 k-halves) -------------
// blocks [0, MMABLK): mma1 path -> Y1 = dinv*(x@W1), x -> hA (tensor cores)
// blocks [MMABLK, MMABLK+E4BLK): atomic-free scatter + g64 zeroing
// smem = 18.4KB (Asm) + 10.2KB (Wsm) = 28.7KB -> 7 blocks/SM occupancy.
#define MMABLK_C 782   // (NNODES + 127) / 128
#define E4BLK_C 1563   // (NEDGES/4 + 255) / 256

__global__ __launch_bounds__(256) void k_scatter_mma1(
    const float* __restrict__ x, const float* __restrict__ W,
    const int4* __restrict__ src4, const int4* __restrict__ dst4) {
    __shared__ __half Asm[128][72];   // 64 k-cols + 8 pad
    __shared__ __half Wsm[128][40];
    int tid = threadIdx.x;

    if (blockIdx.x >= MMABLK_C) {
        // ---- scatter path (touches no smem) ----
        int e = (blockIdx.x - MMABLK_C) * 256 + tid;
        if (e < NGRAPH * 64) d_g64[e] = 0.f;  // zero pooled accum (free ride)
        if (e < NEDGES / 4) {
            int4 s = src4[e];
            int4 d = dst4[e];
            int4 p = reinterpret_cast<const int4*>(d_posin)[e];
            d_col[d_rowptr[d.x] + p.x] = s.x;
            d_col[d_rowptr[d.y] + p.y] = s.y;
            d_col[d_rowptr[d.z] + p.z] = s.z;
            d_col[d_rowptr[d.w] + p.w] = s.w;
        }
        return;
    }

    // ---- mma1 path ----
    for (int i = tid; i < 128 * 32; i += 256)
        Wsm[i >> 5][i & 31] = __float2half(W[i]);

    int row0 = blockIdx.x * 128;
    int warp = tid >> 5, lane = tid & 31;
    float acc[4][4];
#pragma unroll
    for (int i = 0; i < 4; i++)
#pragma unroll
        for (int j = 0; j < 4; j++) acc[i][j] = 0.f;

    uint32_t aBase = smem_u32(&Asm[warp * 16 + (lane & 15)][(lane >> 4) * 8]);

#pragma unroll
    for (int kh = 0; kh < 2; kh++) {
        __syncthreads();
        // load x[:, kh*64 .. kh*64+63] -> Asm (128 rows x 16 float4 each)
        for (int i = tid; i < 128 * 16; i += 256) {
            int r = i >> 4, c4 = i & 15;
            int gr = row0 + r;
            float4 v = (gr < NNODES)
                ? *reinterpret_cast<const float4*>(&x[(size_t)gr * 128 + kh * 64 + c4 * 4])
                : make_float4(0.f, 0.f, 0.f, 0.f);
            __half2 h0 = __floats2half2_rn(v.x, v.y);
            __half2 h1 = __floats2half2_rn(v.z, v.w);
            uint2 pk;
            pk.x = *reinterpret_cast<uint32_t*>(&h0);
            pk.y = *reinterpret_cast<uint32_t*>(&h1);
            *reinterpret_cast<uint2*>(&Asm[r][c4 * 4]) = pk;
        }
        __syncthreads();
#pragma unroll
        for (int ks = 0; ks < 4; ks++) {
            uint32_t a[4];
            ldm_x4(a[0], a[1], a[2], a[3], aBase + ks * 32);
            int krow = kh * 64 + ks * 16;
#pragma unroll
            for (int nb = 0; nb < 2; nb++) {
                uint32_t b[4];
                uint32_t bAddr = smem_u32(&Wsm[krow + (lane & 15)][nb * 16 + (lane >> 4) * 8]);
                ldm_x4t(b[0], b[1], b[2], b[3], bAddr);
                mma16816(acc[nb * 2 + 0], a, b[0], b[1]);
                mma16816(acc[nb * 2 + 1], a, b[2], b[3]);
            }
        }
    }

    int g = lane >> 2, t = lane & 3;
    int n0 = row0 + warp * 16 + g;
    int n1 = n0 + 8;
    float dv0 = (n0 < NNODES) ? d_dinv[n0] : 0.f;
    float dv1 = (n1 < NNODES) ? d_dinv[n1] : 0.f;
#pragma unroll
    for (int nt = 0; nt < 4; nt++) {
        int col = nt * 8 + t * 2;
        if (n0 < NNODES)
            *reinterpret_cast<__half2*>(&d_hA[(size_t)n0 * 32 + col]) =
                __floats2half2_rn(acc[nt][0] * dv0, acc[nt][1] * dv0);
        if (n1 < NNODES)
            *reinterpret_cast<__half2*>(&d_hA[(size_t)n1 * 32 + col]) =
                __floats2half2_rn(acc[nt][2] * dv1, acc[nt][3] * dv1);
    }
}

// ---------------- agg1: P1 = d*relu(d*sum + b1), hA -> hB, F=32 -----------
__launch_bounds__(256)
__global__ void k_agg1(const float* __restrict__ bias) {
    const uint4* __restrict__ Y = (const uint4*)d_hA;
    uint4* __restrict__ O = (uint4*)d_hB;

    int warp = (blockIdx.x * 256 + threadIdx.x) >> 5;
    int lane = threadIdx.x & 31;
    int g = lane >> 2;   // 8 nodes per warp
    int fl = lane & 3;   // 4 lanes per node (16B each)
    int node = warp * 8 + g;
    if (node >= NNODES) return;

    float acc[8];
#pragma unroll
    for (int q = 0; q < 8; q++) acc[q] = 0.f;
    acc8(acc, __ldg(&Y[(size_t)node * 4 + fl]));

    int s = __ldg(&d_rowptr[node]);
    int e = __ldg(&d_rowptr[node + 1]);
    int j = s;
    for (; j + 3 < e; j += 4) {
        int c0 = __ldg(&d_col[j + 0]);
        int c1 = __ldg(&d_col[j + 1]);
        int c2 = __ldg(&d_col[j + 2]);
        int c3 = __ldg(&d_col[j + 3]);
        uint4 v0 = __ldg(&Y[(size_t)c0 * 4 + fl]);
        uint4 v1 = __ldg(&Y[(size_t)c1 * 4 + fl]);
        uint4 v2 = __ldg(&Y[(size_t)c2 * 4 + fl]);
        uint4 v3 = __ldg(&Y[(size_t)c3 * 4 + fl]);
        acc8(acc, v0); acc8(acc, v1); acc8(acc, v2); acc8(acc, v3);
    }
    for (; j < e; j++) {
        int c = __ldg(&d_col[j]);
        acc8(acc, __ldg(&Y[(size_t)c * 4 + fl]));
    }

    float d = d_dinv[node];
    __half2 hv[4];
#pragma unroll
    for (int q = 0; q < 4; q++) {
        float t0 = acc[q * 2 + 0] * d + bias[fl * 8 + q * 2];
        float t1 = acc[q * 2 + 1] * d + bias[fl * 8 + q * 2 + 1];
        t0 = fmaxf(t0, 0.f) * d;
        t1 = fmaxf(t1, 0.f) * d;
        hv[q] = __floats2half2_rn(t0, t1);
    }
    O[(size_t)node * 4 + fl] = *reinterpret_cast<uint4*>(hv);
}

// ---------------- fused agg2 + GEMM2 --------------------------------------
__global__ __launch_bounds__(256) void k_agg2mma2(const float* __restrict__ W,
                                                  const float* __restrict__ bias) {
    __shared__ __half Asm[128][40];
    __shared__ __half Wsm[32][72];
    __shared__ float bsm[64];
    int tid = threadIdx.x;

    for (int i = tid; i < 32 * 64; i += 256)
        Wsm[i >> 6][i & 63] = __float2half(W[i]);
    if (tid < 64) bsm[tid] = bias[tid];

    const uint4* __restrict__ Y = (const uint4*)d_hB;  // P1, 4 uint4/row
    int row0 = blockIdx.x * 128;
    int warp = tid >> 5, lane = tid & 31;

    // phase 1: gather (8 nodes/warp, 4 lanes/node)
    {
        int g = lane >> 2, fl = lane & 3;
#pragma unroll
        for (int pass = 0; pass < 2; pass++) {
            int r = pass * 64 + warp * 8 + g;
            int node = row0 + r;
            float acc[8];
#pragma unroll
            for (int q = 0; q < 8; q++) acc[q] = 0.f;
            if (node < NNODES) {
                acc8(acc, __ldg(&Y[(size_t)node * 4 + fl]));
                int s = __ldg(&d_rowptr[node]);
                int e = __ldg(&d_rowptr[node + 1]);
                int j = s;
                for (; j + 3 < e; j += 4) {
                    int c0 = __ldg(&d_col[j + 0]);
                    int c1 = __ldg(&d_col[j + 1]);
                    int c2 = __ldg(&d_col[j + 2]);
                    int c3 = __ldg(&d_col[j + 3]);
                    uint4 v0 = __ldg(&Y[(size_t)c0 * 4 + fl]);
                    uint4 v1 = __ldg(&Y[(size_t)c1 * 4 + fl]);
                    uint4 v2 = __ldg(&Y[(size_t)c2 * 4 + fl]);
                    uint4 v3 = __ldg(&Y[(size_t)c3 * 4 + fl]);
                    acc8(acc, v0); acc8(acc, v1); acc8(acc, v2); acc8(acc, v3);
                }
                for (; j < e; j++) {
                    int c = __ldg(&d_col[j]);
                    acc8(acc, __ldg(&Y[(size_t)c * 4 + fl]));
                }
                float d = d_dinv[node];
#pragma unroll
                for (int q = 0; q < 8; q++) acc[q] *= d;
            }
            __half2 hv[4];
#pragma unroll
            for (int q = 0; q < 4; q++)
                hv[q] = __floats2half2_rn(acc[q * 2], acc[q * 2 + 1]);
            *reinterpret_cast<uint4*>(&Asm[r][fl * 8]) = *reinterpret_cast<uint4*>(hv);
        }
    }
    __syncthreads();

    // phase 2: tensor-core GEMM
    float accm[8][4];
#pragma unroll
    for (int i = 0; i < 8; i++)
#pragma unroll
        for (int j = 0; j < 4; j++) accm[i][j] = 0.f;

    uint32_t aBase = smem_u32(&Asm[warp * 16 + (lane & 15)][(lane >> 4) * 8]);
#pragma unroll
    for (int ks = 0; ks < 2; ks++) {
        uint32_t a[4];
        ldm_x4(a[0], a[1], a[2], a[3], aBase + ks * 32);
#pragma unroll
        for (int nb = 0; nb < 4; nb++) {
            uint32_t b[4];
            uint32_t bAddr = smem_u32(&Wsm[ks * 16 + (lane & 15)][nb * 16 + (lane >> 4) * 8]);
            ldm_x4t(b[0], b[1], b[2], b[3], bAddr);
            mma16816(accm[nb * 2 + 0], a, b[0], b[1]);
            mma16816(accm[nb * 2 + 1], a, b[2], b[3]);
        }
    }

    int g2 = lane >> 2, t2 = lane & 3;
    int n0 = row0 + warp * 16 + g2;
    int n1 = n0 + 8;
    float dv0 = (n0 < NNODES) ? d_dinv[n0] : 0.f;
    float dv1 = (n1 < NNODES) ? d_dinv[n1] : 0.f;
#pragma unroll
    for (int nt = 0; nt < 8; nt++) {
        int col = nt * 8 + t2 * 2;
        float b0 = bsm[col], b1 = bsm[col + 1];
        if (n0 < NNODES) {
            float t0 = fmaxf(accm[nt][0] + b0, 0.f) * dv0;
            float t1 = fmaxf(accm[nt][1] + b1, 0.f) * dv0;
            *reinterpret_cast<__half2*>(&d_hA[(size_t)n0 * 64 + col]) = __floats2half2_rn(t0, t1);
        }
        if (n1 < NNODES) {
            float t0 = fmaxf(accm[nt][2] + b0, 0.f) * dv1;
            float t1 = fmaxf(accm[nt][3] + b1, 0.f) * dv1;
            *reinterpret_cast<__half2*>(&d_hA[(size_t)n1 * 64 + col]) = __floats2half2_rn(t0, t1);
        }
    }
}

// ---------------- agg3 fused with global_add_pool --------------------------
__launch_bounds__(256)
__global__ void k_agg64pool(const int* __restrict__ batch) {
    const uint4* __restrict__ Y = (const uint4*)d_hA;  // P2, 8 uint4/row
    __shared__ float red[8][64];
    __shared__ int bsh[8];

    int tid = threadIdx.x;
    int warpid = tid >> 5;
    int warp = (blockIdx.x * 256 + tid) >> 5;
    int lane = tid & 31;
    int g = lane >> 3;   // 4 nodes per warp
    int fl = lane & 7;   // 8 lanes per node
    int node = warp * 4 + g;   // exact tiling (100000 % 4 == 0)

    float acc[8];
#pragma unroll
    for (int q = 0; q < 8; q++) acc[q] = 0.f;
    acc8(acc, __ldg(&Y[(size_t)node * 8 + fl]));

    int s = __ldg(&d_rowptr[node]);
    int e = __ldg(&d_rowptr[node + 1]);
    int j = s;
    for (; j + 3 < e; j += 4) {
        int c0 = __ldg(&d_col[j + 0]);
        int c1 = __ldg(&d_col[j + 1]);
        int c2 = __ldg(&d_col[j + 2]);
        int c3 = __ldg(&d_col[j + 3]);
        uint4 v0 = __ldg(&Y[(size_t)c0 * 8 + fl]);
        uint4 v1 = __ldg(&Y[(size_t)c1 * 8 + fl]);
        uint4 v2 = __ldg(&Y[(size_t)c2 * 8 + fl]);
        uint4 v3 = __ldg(&Y[(size_t)c3 * 8 + fl]);
        acc8(acc, v0); acc8(acc, v1); acc8(acc, v2); acc8(acc, v3);
    }
    for (; j < e; j++) {
        int c = __ldg(&d_col[j]);
        acc8(acc, __ldg(&Y[(size_t)c * 8 + fl]));
    }
    float d = d_dinv[node];
#pragma unroll
    for (int q = 0; q < 8; q++) acc[q] *= d;

    int b = __ldg(&batch[node]);
    unsigned m = 0xffffffffu;
    // both shuffles unconditional (no && short-circuit -> no divergent-shfl hang)
    int b8  = __shfl_xor_sync(m, b, 8);
    int b16 = __shfl_xor_sync(m, b, 16);
    bool uni = (b == b8) & (b == b16);
    bool wuni = __all_sync(m, uni);

    if (lane == 0) bsh[warpid] = wuni ? b : -1;
    __syncthreads();
    int b0 = bsh[0];
    bool blockuni = (b0 >= 0);
#pragma unroll
    for (int w = 1; w < 8; w++) blockuni &= (bsh[w] == b0);

    if (blockuni) {
#pragma unroll
        for (int q = 0; q < 8; q++) {
            acc[q] += __shfl_xor_sync(m, acc[q], 8);
            acc[q] += __shfl_xor_sync(m, acc[q], 16);
        }
        if (lane < 8) {
#pragma unroll
            for (int q = 0; q < 8; q++) red[warpid][lane * 8 + q] = acc[q];
        }
    }
    __syncthreads();
    if (blockuni) {
        if (tid < 64) {
            float sum = 0.f;
#pragma unroll
            for (int w = 0; w < 8; w++) sum += red[w][tid];
            atomicAdd(&d_g64[b0 * 64 + tid], sum);
        }
    } else {
        if (wuni) {
#pragma unroll
            for (int q = 0; q < 8; q++) {
                acc[q] += __shfl_xor_sync(m, acc[q], 8);
                acc[q] += __shfl_xor_sync(m, acc[q], 16);
            }
            if (lane < 8) {
                float* gp = &d_g64[b * 64 + fl * 8];
#pragma unroll
                for (int q = 0; q < 8; q++) atomicAdd(&gp[q], acc[q]);
            }
        } else {
            float* gp = &d_g64[b * 64 + fl * 8];
#pragma unroll
            for (int q = 0; q < 8; q++) atomicAdd(&gp[q], acc[q]);
        }
    }
}

// ---------------- GEMM3 (folded) + MLP head + log_softmax ----------------
__global__ void k_mlp(const int* __restrict__ batch,
                      const float* __restrict__ W3, const float* __restrict__ b3,
                      const float* __restrict__ Wl1, const float* __restrict__ bl1,
                      const float* __restrict__ Wl2, const float* __restrict__ bl2,
                      float* __restrict__ out) {
    __shared__ float g[64];
    __shared__ float h3[128];
    __shared__ float hid[64];
    __shared__ float o[10];
    __shared__ int cnt_s;
    int b = blockIdx.x, t = threadIdx.x;
    if (t < 64) g[t] = d_g64[b * 64 + t];
    if (t == 0) {
        int lo = 0, hi = NNODES;
        while (lo < hi) { int m = (lo + hi) >> 1; if (batch[m] < b) lo = m + 1; else hi = m; }
        int lb = lo;
        hi = NNODES;
        while (lo < hi) { int m = (lo + hi) >> 1; if (batch[m] <= b) lo = m + 1; else hi = m; }
        cnt_s = lo - lb;
    }
    __syncthreads();
    float nb = (float)cnt_s;
    {
        float a = nb * b3[t];
        for (int k = 0; k < 64; k++) a += g[k] * W3[k * 128 + t];
        h3[t] = a;
    }
    __syncthreads();
    if (t < 64) {
        float a = bl1[t];
        for (int k = 0; k < 128; k++) a += h3[k] * Wl1[k * 64 + t];
        hid[t] = fmaxf(a, 0.f);
    }
    __syncthreads();
    if (t < 10) {
        float a = bl2[t];
        for (int k = 0; k < 64; k++) a += hid[k] * Wl2[k * 10 + t];
        o[t] = a;
    }
    __syncthreads();
    if (t == 0) {
        float m = -INFINITY;
        for (int i = 0; i < 10; i++) m = fmaxf(m, o[i]);
        float s = 0.f;
        for (int i = 0; i < 10; i++) s += expf(o[i] - m);
        float l = m + logf(s);
        for (int i = 0; i < 10; i++) out[b * 10 + i] = o[i] - l;
    }
}

// ---------------- launch ----------------
extern "C" void kernel_launch(void* const* d_in, const int* in_sizes, int n_in,
                              void* d_out, int out_size) {
    const float* x     = (const float*)d_in[0];
    const int*   ei    = (const int*)d_in[1];
    const int*   batch = (const int*)d_in[2];
    const float* W1  = (const float*)d_in[3];
    const float* b1  = (const float*)d_in[4];
    const float* W2  = (const float*)d_in[5];
    const float* b2  = (const float*)d_in[6];
    const float* W3  = (const float*)d_in[7];
    const float* b3  = (const float*)d_in[8];
    const float* Wl1 = (const float*)d_in[9];
    const float* bl1 = (const float*)d_in[10];
    const float* Wl2 = (const float*)d_in[11];
    const float* bl2 = (const float*)d_in[12];
    float* out = (float*)d_out;

    const int4* src4 = (const int4*)ei;
    const int4* dst4 = (const int4*)(ei + NEDGES);

    const int NBLK_SCAN = (NNODES + 511) / 512;                // 196
    const int E4BLK = (NEDGES / 4 + 255) / 256;                // 1563
    const int AGG32_BLK = ((NNODES + 7) / 8 * 32 + 255) / 256; // 1563
    const int AGG64_BLK = (NNODES / 4 * 32) / 256;             // 3125 (exact)
    const int MMABLK = (NNODES + 127) / 128;                   // 782

    // CSR prefix (deg zeroed by previous call's k_scan3 / module-load init)
    k_degpos<<<E4BLK, 256>>>(dst4);
    k_scan1<<<NBLK_SCAN, 512>>>();
    k_scan3<<<NBLK_SCAN, 512>>>(NBLK_SCAN);

    // fused: scatter (CSR col build) overlapped with L1 GEMM  -> d_col, hA
    k_scatter_mma1<<<MMABLK + E4BLK, 256>>>(x, W1, src4, dst4);

    // agg1: P1 = d*relu(d*sum + b1)          hA -> hB
    k_agg1<<<AGG32_BLK, 256>>>(b1);
    // fused agg2+L2: P2 = d*relu((d*sum)@W2+b2)  hB -> hA
    k_agg2mma2<<<MMABLK, 256>>>(W2, b2);
    // agg3 + pool: g64 += d*sum(P2)          hA -> d_g64
    k_agg64pool<<<AGG64_BLK, 256>>>(batch);

    // folded GEMM3 + MLP head
    k_mlp<<<NGRAPH, 128>>>(batch, W3, b3, Wl1, bl1, Wl2, bl2, out);
}